// round 14
// baseline (speedup 1.0000x reference)
#include <cuda_runtime.h>
#include <stdint.h>

#define BATCH   2
#define SEQ     2048
#define DIM     1024
#define NHEAD   16
#define HDIM    64
#define MAXLEN  2048
#define BN      (BATCH*SEQ)

// ---------------- scratch (device globals; allocation is forbidden) ----------------
__device__ float g_Q[(size_t)BATCH * NHEAD * SEQ * HDIM];   // [(b*H+h)][n][hd]
__device__ float g_K[(size_t)BATCH * NHEAD * SEQ * HDIM];
__device__ float g_V[(size_t)BATCH * NHEAD * SEQ * HDIM];
__device__ float g_O[(size_t)BATCH * SEQ * DIM];            // [b][n][h*HD+hd]

// ---------------- helpers ----------------
__device__ __forceinline__ uint32_t f2t(float f) {
    uint32_t u;
    asm("cvt.rna.tf32.f32 %0, %1;" : "=r"(u) : "f"(f));
    return u;
}
__device__ __forceinline__ float f2tf(float f) {
    return __uint_as_float(f2t(f));
}
__device__ __forceinline__ void mma8(float c[4],
                                     uint32_t a0, uint32_t a1, uint32_t a2, uint32_t a3,
                                     uint32_t b0, uint32_t b1) {
    asm volatile(
        "mma.sync.aligned.m16n8k8.row.col.f32.tf32.tf32.f32 "
        "{%0,%1,%2,%3},{%4,%5,%6,%7},{%8,%9},{%0,%1,%2,%3};"
        : "+f"(c[0]), "+f"(c[1]), "+f"(c[2]), "+f"(c[3])
        : "r"(a0), "r"(a1), "r"(a2), "r"(a3), "r"(b0), "r"(b1));
}
#define U(x) __float_as_uint(x)

// chunk swizzle for 64-word permuted rows
__device__ __forceinline__ int swz(int row) {
    return ((row & 1) << 2) | ((row >> 1) & 3);
}
// store float4 holding gmem k = c4..c4+3 into a permuted 64-word row
__device__ __forceinline__ void stash_perm(float* rowp, int c4, float4 v, int s) {
    int a4 = 4 * (c4 >> 4);
    int wd = (c4 & 15) >> 2;
    rowp[4 * ((a4 + 0) ^ s) + wd] = v.x;
    rowp[4 * ((a4 + 1) ^ s) + wd] = v.y;
    rowp[4 * ((a4 + 2) ^ s) + wd] = v.z;
    rowp[4 * ((a4 + 3) ^ s) + wd] = v.w;
}
// one LDS.128: (x,y,z,w) = k(16kb+t), k(16kb+t+4), k(16kb+t+8), k(16kb+t+12)
__device__ __forceinline__ float4 frag4(const float* S, int stride, int row, int kb, int t) {
    return *(const float4*)&S[row * stride + 4 * ((4 * kb + t) ^ swz(row))];
}

// ---------------- GEMM: C[m,n] = sum_k A[m,k] * W[n,k], 1x tf32 ----------------
// (R12 proven version: permuted-k + XOR swizzle, double-buffered)
template<int MODE>
__global__ __launch_bounds__(256, 2)
void gemm_tn(const float* __restrict__ Aext,
             const float* __restrict__ W0, const float* __restrict__ W1,
             const float* __restrict__ W2,
             const float* __restrict__ bias, float* __restrict__ Cext)
{
    __align__(16) __shared__ float As[2][128 * 16];   // tf32 bits, swizzled
    __align__(16) __shared__ float Bs[2][128 * 16];

    const int sel = (MODE == 1) ? blockIdx.z : 0;
    const float* W = (MODE == 0) ? W0 : ((sel == 0) ? W0 : (sel == 1) ? W1 : W2);
    const float* A = (MODE == 0) ? (const float*)g_O : Aext;

    const int m0 = blockIdx.y * 128;
    const int n0 = blockIdx.x * 128;
    const int tid = threadIdx.x;
    const int w = tid >> 5, lane = tid & 31, g = lane >> 2, t = lane & 3;
    const int wy = w >> 2, wx = w & 3;   // 2x4 warp grid; warp tile 64x32

    const int srow = tid >> 2;
    const int sc   = tid & 3;
    const int sxb  = (srow >> 1) & 3;

    float acc[4][4][4];
#pragma unroll
    for (int i = 0; i < 4; i++)
#pragma unroll
        for (int j = 0; j < 4; j++)
#pragma unroll
            for (int e = 0; e < 4; e++) acc[i][j][e] = 0.f;

    auto stage = [&](float* S, int row, float4 v) {
        float* base = S + row * 16 + sc;
        base[4 * (0 ^ sxb)] = f2tf(v.x);
        base[4 * (1 ^ sxb)] = f2tf(v.y);
        base[4 * (2 ^ sxb)] = f2tf(v.z);
        base[4 * (3 ^ sxb)] = f2tf(v.w);
    };

    float4 ra0, ra1, rb0, rb1;
    ra0 = *(const float4*)(A + (size_t)(m0 + srow)      * DIM + 4 * sc);
    ra1 = *(const float4*)(A + (size_t)(m0 + srow + 64) * DIM + 4 * sc);
    rb0 = *(const float4*)(W + (size_t)(n0 + srow)      * DIM + 4 * sc);
    rb1 = *(const float4*)(W + (size_t)(n0 + srow + 64) * DIM + 4 * sc);
    stage(As[0], srow,      ra0);
    stage(As[0], srow + 64, ra1);
    stage(Bs[0], srow,      rb0);
    stage(Bs[0], srow + 64, rb1);
    __syncthreads();

    int cur = 0;
    for (int k0 = 0; k0 < DIM; k0 += 16, cur ^= 1) {
        const bool more = (k0 + 16 < DIM);
        if (more) {
            ra0 = *(const float4*)(A + (size_t)(m0 + srow)      * DIM + k0 + 16 + 4 * sc);
            ra1 = *(const float4*)(A + (size_t)(m0 + srow + 64) * DIM + k0 + 16 + 4 * sc);
            rb0 = *(const float4*)(W + (size_t)(n0 + srow)      * DIM + k0 + 16 + 4 * sc);
            rb1 = *(const float4*)(W + (size_t)(n0 + srow + 64) * DIM + k0 + 16 + 4 * sc);
        }

        float4 fa[4][2], fb[4];
#pragma unroll
        for (int mt = 0; mt < 4; mt++) {
            int r = wy * 64 + mt * 16 + g;
            fa[mt][0] = *(float4*)&As[cur][r * 16 + 4 * (t ^ ((r >> 1) & 3))];
            int r2 = r + 8;
            fa[mt][1] = *(float4*)&As[cur][r2 * 16 + 4 * (t ^ ((r2 >> 1) & 3))];
        }
#pragma unroll
        for (int nt = 0; nt < 4; nt++) {
            int c = wx * 32 + nt * 8 + g;
            fb[nt] = *(float4*)&Bs[cur][c * 16 + 4 * (t ^ ((c >> 1) & 3))];
        }

#pragma unroll
        for (int mt = 0; mt < 4; mt++)
#pragma unroll
            for (int nt = 0; nt < 4; nt++) {
                mma8(acc[mt][nt], U(fa[mt][0].x), U(fa[mt][1].x),
                                  U(fa[mt][0].y), U(fa[mt][1].y),
                                  U(fb[nt].x),    U(fb[nt].y));
                mma8(acc[mt][nt], U(fa[mt][0].z), U(fa[mt][1].z),
                                  U(fa[mt][0].w), U(fa[mt][1].w),
                                  U(fb[nt].z),    U(fb[nt].w));
            }

        if (more) {
            stage(As[cur ^ 1], srow,      ra0);
            stage(As[cur ^ 1], srow + 64, ra1);
            stage(Bs[cur ^ 1], srow,      rb0);
            stage(Bs[cur ^ 1], srow + 64, rb1);
        }
        __syncthreads();
    }

    float* dstQKV = (MODE == 1) ? ((sel == 0) ? g_Q : ((sel == 1) ? g_K : g_V)) : nullptr;
#pragma unroll
    for (int mt = 0; mt < 4; mt++) {
        int rbase = wy * 64 + mt * 16 + g;
#pragma unroll
        for (int nt = 0; nt < 4; nt++) {
            int cbase = wx * 32 + nt * 8 + 2 * t;
#pragma unroll
            for (int e = 0; e < 4; e++) {
                int gm = m0 + rbase + ((e >= 2) ? 8 : 0);
                int gn = n0 + cbase + (e & 1);
                float v = acc[mt][nt][e];
                if (MODE == 0) {
                    Cext[(size_t)gm * DIM + gn] = v + bias[gn];
                } else {
                    int bb = gm / SEQ, nrow = gm % SEQ;
                    int hh = gn / HDIM, hd = gn % HDIM;
                    dstQKV[(((size_t)bb * NHEAD + hh) * SEQ + nrow) * HDIM + hd] = v;
                }
            }
        }
    }
}

// ---------------- fused causal attention with skewed relative positions ----------------
// srel[r,c] = q_{r-1} . e_{N-(r-c)} for c<r, 0 at c==r (via zero-filled E rows >= N).
// sQ/sK/sE: permuted 64-word rows. sVT: V TRANSPOSED [hd][token], permuted -> PV uses LDS.128.
// sE ring: 64 new rows staged per k-tile. P permuted into dead sQ region.
#define GBW 65
#define ATTN_SMEM_FLOATS (65*64 + 64*64 + 64*64 + 128*64 + 64*GBW)
#define ATTN_SMEM_BYTES  (ATTN_SMEM_FLOATS * 4)

__global__ __launch_bounds__(128, 2)
void attn_kernel(const float* __restrict__ rel)
{
    extern __shared__ float sm[];
    float* sQ  = sm;                    // [65][64] perm tf32; reused as P
    float* sK  = sQ + 65 * 64;          // [64][64] perm raw fp32
    float* sVT = sK + 64 * 64;          // [64][64] perm tf32, V^T (row=hd, col=token)
    float* sE  = sVT + 64 * 64;         // [128][64] perm raw fp32, ring
    float* sGb = sE + 128 * 64;         // [64][GBW] G band (scalar)
    float* sP  = sQ;

    const int qt = (gridDim.x - 1) - blockIdx.x;   // 31..0 (long CTAs first)
    const int bh = blockIdx.y;
    const int r0 = qt * 64;
    const int b  = bh / NHEAD;
    const int h  = bh % NHEAD;
    const int hcol = h * HDIM;

    const float* Qg = g_Q + (size_t)bh * SEQ * HDIM;
    const float* Kg = g_K + (size_t)bh * SEQ * HDIM;
    const float* Vg = g_V + (size_t)bh * SEQ * HDIM;

    const int tid = threadIdx.x;
    const int w = tid >> 5, lane = tid & 31, g = lane >> 2, t = lane & 3;
    const int rA = w * 16 + g;

    for (int idx = tid; idx < 65 * 16; idx += 128) {
        int row = idx >> 4, c4 = (idx & 15) << 2;
        int gr = r0 - 1 + row; if (gr < 0) gr = 0;
        float4 v = *(const float4*)(Qg + (size_t)gr * HDIM + c4);
        stash_perm(sQ + row * 64, c4,
                   make_float4(f2tf(v.x), f2tf(v.y), f2tf(v.z), f2tf(v.w)),
                   swz(row));
    }
    __syncthreads();

    uint32_t aQ[8][4], aQp[8][4];
#pragma unroll
    for (int kb = 0; kb < 4; kb++) {
        float4 f;
        f = frag4(sQ, 64, 1 + rA, kb, t);
        aQ[2*kb][0] = U(f.x); aQ[2*kb][2] = U(f.y);
        aQ[2*kb+1][0] = U(f.z); aQ[2*kb+1][2] = U(f.w);
        f = frag4(sQ, 64, 9 + rA, kb, t);
        aQ[2*kb][1] = U(f.x); aQ[2*kb][3] = U(f.y);
        aQ[2*kb+1][1] = U(f.z); aQ[2*kb+1][3] = U(f.w);
        f = frag4(sQ, 64, rA, kb, t);
        aQp[2*kb][0] = U(f.x); aQp[2*kb][2] = U(f.y);
        aQp[2*kb+1][0] = U(f.z); aQp[2*kb+1][2] = U(f.w);
        f = frag4(sQ, 64, 8 + rA, kb, t);
        aQp[2*kb][1] = U(f.x); aQp[2*kb][3] = U(f.y);
        aQp[2*kb+1][1] = U(f.z); aQp[2*kb+1][3] = U(f.w);
    }

    float Oacc[8][4];
#pragma unroll
    for (int i = 0; i < 8; i++)
#pragma unroll
        for (int e = 0; e < 4; e++) Oacc[i][e] = 0.f;
    float m0r = -1e30f, m1r = -1e30f;
    float l0r = 0.f,    l1r = 0.f;

    for (int j = 0; j <= qt; j++) {
        const int c0 = j * 64;
        const int ph = (j & 1) << 6;
        __syncthreads();

        // K: perm raw fp32 (coalesced LDG)
        for (int idx = tid; idx < 64 * 16; idx += 128) {
            int row = idx >> 4, c4 = (idx & 15) << 2;
            float4 kv = *(const float4*)(Kg + (size_t)(c0 + row) * HDIM + c4);
            stash_perm(sK + row * 64, c4, kv, swz(row));
        }
        // V transposed: lanes stride tokens (conflict-free scatter STS)
        for (int idx = tid; idx < 64 * 16; idx += 128) {
            int tok = idx & 63, c4 = (idx >> 6) << 2;
            float4 vv = *(const float4*)(Vg + (size_t)(c0 + tok) * HDIM + c4);
            float vals[4] = {f2tf(vv.x), f2tf(vv.y), f2tf(vv.z), f2tf(vv.w)};
            int chn = 4 * (tok >> 4) + (tok & 3);
            int wd  = (tok & 15) >> 2;
#pragma unroll
            for (int i = 0; i < 4; i++) {
                int r = c4 + i;
                sVT[r * 64 + 4 * (chn ^ swz(r)) + wd] = vals[i];
            }
        }
        // E ring: perm raw fp32
        const int elog0 = SEQ - r0 + c0 - 63;
        const int rbase = (j == 0) ? 0 : 64;
        for (int idx = tid; idx < (128 - rbase) * 16; idx += 128) {
            int row = rbase + (idx >> 4), c4 = (idx & 15) << 2;
            int el = elog0 + row;
            float4 ev = make_float4(0.f, 0.f, 0.f, 0.f);
            if (el < SEQ)
                ev = *(const float4*)(rel + (size_t)(el + (MAXLEN - SEQ)) * DIM + hcol + c4);
            int pr = row ^ ph;
            stash_perm(sE + pr * 64, c4, ev, swz(pr));
        }
        __syncthreads();

        // G band = Qprev @ Ewin^T (warp-trimmed)
        const int nt0 = 6 - 2 * w;
#pragma unroll
        for (int ntl = 0; ntl < 10; ntl++) {
            const int nt = nt0 + ntl;
            float ga[4] = {0.f, 0.f, 0.f, 0.f};
            const int pr = (nt * 8 + g) ^ ph;
            float4 f0 = frag4(sE, 64, pr, 0, t);
            float4 f1 = frag4(sE, 64, pr, 1, t);
            float4 f2 = frag4(sE, 64, pr, 2, t);
            float4 f3 = frag4(sE, 64, pr, 3, t);
            mma8(ga, aQp[0][0], aQp[0][1], aQp[0][2], aQp[0][3], U(f0.x), U(f0.y));
            mma8(ga, aQp[1][0], aQp[1][1], aQp[1][2], aQp[1][3], U(f0.z), U(f0.w));
            mma8(ga, aQp[2][0], aQp[2][1], aQp[2][2], aQp[2][3], U(f1.x), U(f1.y));
            mma8(ga, aQp[3][0], aQp[3][1], aQp[3][2], aQp[3][3], U(f1.z), U(f1.w));
            mma8(ga, aQp[4][0], aQp[4][1], aQp[4][2], aQp[4][3], U(f2.x), U(f2.y));
            mma8(ga, aQp[5][0], aQp[5][1], aQp[5][2], aQp[5][3], U(f2.z), U(f2.w));
            mma8(ga, aQp[6][0], aQp[6][1], aQp[6][2], aQp[6][3], U(f3.x), U(f3.y));
            mma8(ga, aQp[7][0], aQp[7][1], aQp[7][2], aQp[7][3], U(f3.z), U(f3.w));
            const int cc = nt * 8 + 2 * t;
            const int i0 = cc + rA - 63;
            const int i2 = i0 + 8;
            if (i0 >= 0     && i0 < 64)     sGb[(rA)     * GBW + i0]     = ga[0];
            if (i0 + 1 >= 0 && i0 + 1 < 64) sGb[(rA)     * GBW + i0 + 1] = ga[1];
            if (i2 >= 0     && i2 < 64)     sGb[(rA + 8) * GBW + i2]     = ga[2];
            if (i2 + 1 >= 0 && i2 + 1 < 64) sGb[(rA + 8) * GBW + i2 + 1] = ga[3];
        }
        __syncwarp();

        // S = Q @ K^T + srel (band gather), mask, scale
        float Sreg[8][4];
        float tmax0 = -1e30f, tmax1 = -1e30f;
#pragma unroll
        for (int nt = 0; nt < 8; nt++) {
            float* s = Sreg[nt];
            s[0] = s[1] = s[2] = s[3] = 0.f;
            const int kr = nt * 8 + g;
            float4 f0 = frag4(sK, 64, kr, 0, t);
            float4 f1 = frag4(sK, 64, kr, 1, t);
            float4 f2 = frag4(sK, 64, kr, 2, t);
            float4 f3 = frag4(sK, 64, kr, 3, t);
            mma8(s, aQ[0][0], aQ[0][1], aQ[0][2], aQ[0][3], U(f0.x), U(f0.y));
            mma8(s, aQ[1][0], aQ[1][1], aQ[1][2], aQ[1][3], U(f0.z), U(f0.w));
            mma8(s, aQ[2][0], aQ[2][1], aQ[2][2], aQ[2][3], U(f1.x), U(f1.y));
            mma8(s, aQ[3][0], aQ[3][1], aQ[3][2], aQ[3][3], U(f1.z), U(f1.w));
            mma8(s, aQ[4][0], aQ[4][1], aQ[4][2], aQ[4][3], U(f2.x), U(f2.y));
            mma8(s, aQ[5][0], aQ[5][1], aQ[5][2], aQ[5][3], U(f2.z), U(f2.w));
            mma8(s, aQ[6][0], aQ[6][1], aQ[6][2], aQ[6][3], U(f3.x), U(f3.y));
            mma8(s, aQ[7][0], aQ[7][1], aQ[7][2], aQ[7][3], U(f3.z), U(f3.w));

            const int cc0 = nt * 8 + 2 * t;
            float v;
            v = (s[0] + sGb[rA * GBW + cc0]) * 0.125f;
            if (c0 + cc0 > r0 + rA) v = -1e30f;
            s[0] = v; tmax0 = fmaxf(tmax0, v);

            v = (s[1] + sGb[rA * GBW + cc0 + 1]) * 0.125f;
            if (c0 + cc0 + 1 > r0 + rA) v = -1e30f;
            s[1] = v; tmax0 = fmaxf(tmax0, v);

            v = (s[2] + sGb[(rA + 8) * GBW + cc0]) * 0.125f;
            if (c0 + cc0 > r0 + rA + 8) v = -1e30f;
            s[2] = v; tmax1 = fmaxf(tmax1, v);

            v = (s[3] + sGb[(rA + 8) * GBW + cc0 + 1]) * 0.125f;
            if (c0 + cc0 + 1 > r0 + rA + 8) v = -1e30f;
            s[3] = v; tmax1 = fmaxf(tmax1, v);
        }

        tmax0 = fmaxf(tmax0, __shfl_xor_sync(0xffffffffu, tmax0, 1));
        tmax0 = fmaxf(tmax0, __shfl_xor_sync(0xffffffffu, tmax0, 2));
        tmax1 = fmaxf(tmax1, __shfl_xor_sync(0xffffffffu, tmax1, 1));
        tmax1 = fmaxf(tmax1, __shfl_xor_sync(0xffffffffu, tmax1, 2));

        float mn0 = fmaxf(m0r, tmax0), mn1 = fmaxf(m1r, tmax1);
        float f0s = __expf(m0r - mn0), f1s = __expf(m1r - mn1);
        float rs0 = 0.f, rs1 = 0.f;
#pragma unroll
        for (int nt = 0; nt < 8; nt++) {
            float* s = Sreg[nt];
            s[0] = __expf(s[0] - mn0); s[1] = __expf(s[1] - mn0);
            s[2] = __expf(s[2] - mn1); s[3] = __expf(s[3] - mn1);
            rs0 += s[0] + s[1];
            rs1 += s[2] + s[3];
        }
        rs0 += __shfl_xor_sync(0xffffffffu, rs0, 1);
        rs0 += __shfl_xor_sync(0xffffffffu, rs0, 2);
        rs1 += __shfl_xor_sync(0xffffffffu, rs1, 1);
        rs1 += __shfl_xor_sync(0xffffffffu, rs1, 2);

        m0r = mn0; m1r = mn1;
        l0r = l0r * f0s + rs0;
        l1r = l1r * f1s + rs1;
#pragma unroll
        for (int dn = 0; dn < 8; dn++) {
            Oacc[dn][0] *= f0s; Oacc[dn][1] *= f0s;
            Oacc[dn][2] *= f1s; Oacc[dn][3] *= f1s;
        }

        __syncwarp();
#pragma unroll
        for (int nt = 0; nt < 8; nt++) {
            int c = nt * 8 + 2 * t;
            int ch = 4 * (c >> 4) + (c & 3);
            int wd = (c & 15) >> 2;
            int s0 = swz(rA), s1 = swz(rA + 8);
            sP[(rA)     * 64 + 4 * ((ch)     ^ s0) + wd] = f2tf(Sreg[nt][0]);
            sP[(rA)     * 64 + 4 * ((ch + 1) ^ s0) + wd] = f2tf(Sreg[nt][1]);
            sP[(rA + 8) * 64 + 4 * ((ch)     ^ s1) + wd] = f2tf(Sreg[nt][2]);
            sP[(rA + 8) * 64 + 4 * ((ch + 1) ^ s1) + wd] = f2tf(Sreg[nt][3]);
        }
        __syncwarp();

        uint32_t aP[8][4];
#pragma unroll
        for (int kb = 0; kb < 4; kb++) {
            float4 f;
            f = frag4(sP, 64, rA, kb, t);
            aP[2*kb][0] = U(f.x); aP[2*kb][2] = U(f.y);
            aP[2*kb+1][0] = U(f.z); aP[2*kb+1][2] = U(f.w);
            f = frag4(sP, 64, rA + 8, kb, t);
            aP[2*kb][1] = U(f.x); aP[2*kb][3] = U(f.y);
            aP[2*kb+1][1] = U(f.z); aP[2*kb+1][3] = U(f.w);
        }

        // O += P @ V  (V^T fragments via LDS.128)
#pragma unroll
        for (int dn = 0; dn < 8; dn++) {
            const int nb = dn * 8 + g;
            float4 v0 = frag4(sVT, 64, nb, 0, t);
            float4 v1 = frag4(sVT, 64, nb, 1, t);
            float4 v2 = frag4(sVT, 64, nb, 2, t);
            float4 v3 = frag4(sVT, 64, nb, 3, t);
            mma8(Oacc[dn], aP[0][0], aP[0][1], aP[0][2], aP[0][3], U(v0.x), U(v0.y));
            mma8(Oacc[dn], aP[1][0], aP[1][1], aP[1][2], aP[1][3], U(v0.z), U(v0.w));
            mma8(Oacc[dn], aP[2][0], aP[2][1], aP[2][2], aP[2][3], U(v1.x), U(v1.y));
            mma8(Oacc[dn], aP[3][0], aP[3][1], aP[3][2], aP[3][3], U(v1.z), U(v1.w));
            mma8(Oacc[dn], aP[4][0], aP[4][1], aP[4][2], aP[4][3], U(v2.x), U(v2.y));
            mma8(Oacc[dn], aP[5][0], aP[5][1], aP[5][2], aP[5][3], U(v2.z), U(v2.w));
            mma8(Oacc[dn], aP[6][0], aP[6][1], aP[6][2], aP[6][3], U(v3.x), U(v3.y));
            mma8(Oacc[dn], aP[7][0], aP[7][1], aP[7][2], aP[7][3], U(v3.z), U(v3.w));
        }
    }

    // normalize and write O in [b][n][h*HD+hd] layout
    float inv0 = 1.f / l0r, inv1 = 1.f / l1r;
    float* Og = g_O + (size_t)b * SEQ * DIM + (size_t)r0 * DIM + hcol;
#pragma unroll
    for (int dn = 0; dn < 8; dn++) {
        int d0 = dn * 8 + 2 * t;
        Og[(size_t)(rA)     * DIM + d0]     = Oacc[dn][0] * inv0;
        Og[(size_t)(rA)     * DIM + d0 + 1] = Oacc[dn][1] * inv0;
        Og[(size_t)(rA + 8) * DIM + d0]     = Oacc[dn][2] * inv1;
        Og[(size_t)(rA + 8) * DIM + d0 + 1] = Oacc[dn][3] * inv1;
    }
}

// ---------------- launch ----------------
extern "C" void kernel_launch(void* const* d_in, const int* in_sizes, int n_in,
                              void* d_out, int out_size)
{
    const float* x   = (const float*)d_in[0];
    const float* Wq  = (const float*)d_in[1];
    const float* Wk  = (const float*)d_in[2];
    const float* Wv  = (const float*)d_in[3];
    const float* Wp  = (const float*)d_in[4];
    const float* bp  = (const float*)d_in[5];
    const float* rel = (const float*)d_in[6];
    float* out = (float*)d_out;

    cudaFuncSetAttribute(attn_kernel,
                         cudaFuncAttributeMaxDynamicSharedMemorySize,
                         ATTN_SMEM_BYTES);

    gemm_tn<1><<<dim3(DIM / 128, BN / 128, 3), 256>>>(x, Wq, Wk, Wv, nullptr, nullptr);
    attn_kernel<<<dim3(SEQ / 64, BATCH * NHEAD), 128, ATTN_SMEM_BYTES>>>(rel);
    gemm_tn<0><<<dim3(DIM / 128, BN / 128), 256>>>(nullptr, Wp, nullptr, nullptr, bp, out);
}

// round 15
// speedup vs baseline: 1.5232x; 1.5232x over previous
#include <cuda_runtime.h>
#include <stdint.h>

#define BATCH   2
#define SEQ     2048
#define DIM     1024
#define NHEAD   16
#define HDIM    64
#define MAXLEN  2048
#define BN      (BATCH*SEQ)

// ---------------- scratch (device globals; allocation is forbidden) ----------------
__device__ float g_Q[(size_t)BATCH * NHEAD * SEQ * HDIM];   // [(b*H+h)][n][hd]
__device__ float g_K[(size_t)BATCH * NHEAD * SEQ * HDIM];
__device__ float g_V[(size_t)BATCH * NHEAD * SEQ * HDIM];
__device__ float g_O[(size_t)BATCH * SEQ * DIM];            // raw fp32, [b][n][h*HD+hd]
// permuted + RNA-tf32 copies in the exact gemm smem image layout
__device__ float g_xp [(size_t)BN * DIM];
__device__ float g_Wqp[(size_t)DIM * DIM];
__device__ float g_Wkp[(size_t)DIM * DIM];
__device__ float g_Wvp[(size_t)DIM * DIM];
__device__ float g_Wpp[(size_t)DIM * DIM];

// ---------------- helpers ----------------
__device__ __forceinline__ uint32_t f2t(float f) {
    uint32_t u;
    asm("cvt.rna.tf32.f32 %0, %1;" : "=r"(u) : "f"(f));
    return u;
}
__device__ __forceinline__ float f2tf(float f) {
    return __uint_as_float(f2t(f));
}
__device__ __forceinline__ void mma8(float c[4],
                                     uint32_t a0, uint32_t a1, uint32_t a2, uint32_t a3,
                                     uint32_t b0, uint32_t b1) {
    asm volatile(
        "mma.sync.aligned.m16n8k8.row.col.f32.tf32.tf32.f32 "
        "{%0,%1,%2,%3},{%4,%5,%6,%7},{%8,%9},{%0,%1,%2,%3};"
        : "+f"(c[0]), "+f"(c[1]), "+f"(c[2]), "+f"(c[3])
        : "r"(a0), "r"(a1), "r"(a2), "r"(a3), "r"(b0), "r"(b1));
}
#define U(x) __float_as_uint(x)

__device__ __forceinline__ void cp16(uint32_t saddr, const float* gptr) {
    asm volatile("cp.async.cg.shared.global [%0], [%1], 16;" :: "r"(saddr), "l"(gptr));
}
#define CP_COMMIT() asm volatile("cp.async.commit_group;")

// chunk swizzle for attention's 64-word permuted rows
__device__ __forceinline__ int swz(int row) {
    return ((row & 1) << 2) | ((row >> 1) & 3);
}
__device__ __forceinline__ void stash_perm(float* rowp, int c4, float4 v, int s) {
    int a4 = 4 * (c4 >> 4);
    int wd = (c4 & 15) >> 2;
    rowp[4 * ((a4 + 0) ^ s) + wd] = v.x;
    rowp[4 * ((a4 + 1) ^ s) + wd] = v.y;
    rowp[4 * ((a4 + 2) ^ s) + wd] = v.z;
    rowp[4 * ((a4 + 3) ^ s) + wd] = v.w;
}
__device__ __forceinline__ float4 frag4(const float* S, int stride, int row, int kb, int t) {
    return *(const float4*)&S[row * stride + 4 * ((4 * kb + t) ^ swz(row))];
}

// ---------------- prologue: permute + RNA-cvt into the gemm smem image ----------------
// word(k) within a 16-word group = 4*((k&3)^sxb) + (k>>2), sxb = (row>>1)&3
__global__ void permute_cvt(const float* __restrict__ src, float* __restrict__ dst,
                            int ngroups)
{
    int gi = blockIdx.x * 256 + threadIdx.x;
    if (gi >= ngroups) return;
    int row = gi >> 6;                 // 64 groups of 16 words per 1024-wide row
    int sxb = (row >> 1) & 3;
    const float4* s = (const float4*)(src + (size_t)gi * 16);
    float4 v0 = s[0], v1 = s[1], v2 = s[2], v3 = s[3];
    float4* d = (float4*)(dst + (size_t)gi * 16);
    d[0 ^ sxb] = make_float4(f2tf(v0.x), f2tf(v1.x), f2tf(v2.x), f2tf(v3.x));
    d[1 ^ sxb] = make_float4(f2tf(v0.y), f2tf(v1.y), f2tf(v2.y), f2tf(v3.y));
    d[2 ^ sxb] = make_float4(f2tf(v0.z), f2tf(v1.z), f2tf(v2.z), f2tf(v3.z));
    d[3 ^ sxb] = make_float4(f2tf(v0.w), f2tf(v1.w), f2tf(v2.w), f2tf(v3.w));
}

// ---------------- GEMM: C[m,n] = sum_k A[m,k] * W[n,k], 1x tf32 ----------------
// MODE 1: A = g_xp (cp.async), B = g_W{q,k,v}p by blockIdx.z (cp.async); scatter QKV.
// MODE 0: A = g_O raw (LDG+cvt+STS), B = g_Wpp (cp.async); C = out + bias.
template<int MODE>
__global__ __launch_bounds__(256, 2)
void gemm_tn(const float* __restrict__ B0, const float* __restrict__ B1,
             const float* __restrict__ B2,
             const float* __restrict__ bias, float* __restrict__ Cext)
{
    __align__(16) __shared__ float As[2][128 * 16];
    __align__(16) __shared__ float Bs[2][128 * 16];

    const int sel = (MODE == 1) ? blockIdx.z : 0;
    const float* Bp = (sel == 0) ? B0 : ((sel == 1) ? B1 : B2);

    const int m0 = blockIdx.y * 128;
    const int n0 = blockIdx.x * 128;
    const int tid = threadIdx.x;
    const int w = tid >> 5, lane = tid & 31, g = lane >> 2, t = lane & 3;
    const int wy = w >> 2, wx = w & 3;   // 2x4 warp grid; warp tile 64x32

    const uint32_t sA = (uint32_t)__cvta_generic_to_shared(&As[0][0]);
    const uint32_t sB = (uint32_t)__cvta_generic_to_shared(&Bs[0][0]);

    // MODE0 A staging (R12 path)
    const int srow = tid >> 2;
    const int sc   = tid & 3;
    const int sxb  = (srow >> 1) & 3;
    auto stageA = [&](float* S, int row, float4 v) {
        float* base = S + row * 16 + sc;
        base[4 * (0 ^ sxb)] = f2tf(v.x);
        base[4 * (1 ^ sxb)] = f2tf(v.y);
        base[4 * (2 ^ sxb)] = f2tf(v.z);
        base[4 * (3 ^ sxb)] = f2tf(v.w);
    };

    // cp.async issue: 512 16B-chunks per matrix per k-block; 2 chunks/thread
    auto issueB = [&](int buf, int kb) {
#pragma unroll
        for (int r = 0; r < 2; r++) {
            int ch = tid + 256 * r;
            int row = ch >> 2, wg = ch & 3;
            cp16(sB + (uint32_t)(buf * 2048 + 4 * ch) * 4,
                 Bp + (size_t)(n0 + row) * DIM + kb * 16 + wg * 4);
        }
    };
    auto issueA = [&](int buf, int kb) {
#pragma unroll
        for (int r = 0; r < 2; r++) {
            int ch = tid + 256 * r;
            int row = ch >> 2, wg = ch & 3;
            cp16(sA + (uint32_t)(buf * 2048 + 4 * ch) * 4,
                 g_xp + (size_t)(m0 + row) * DIM + kb * 16 + wg * 4);
        }
    };

    float acc[4][4][4];
#pragma unroll
    for (int i = 0; i < 4; i++)
#pragma unroll
        for (int j = 0; j < 4; j++)
#pragma unroll
            for (int e = 0; e < 4; e++) acc[i][j][e] = 0.f;

    float4 ra0, ra1;
    // prologue: stage k-block 0
    if (MODE == 1) {
        issueA(0, 0);
        issueB(0, 0);
        CP_COMMIT();
        asm volatile("cp.async.wait_group 0;");
        __syncthreads();
    } else {
        issueB(0, 0);
        CP_COMMIT();
        ra0 = *(const float4*)(g_O + (size_t)(m0 + srow)      * DIM + 4 * sc);
        ra1 = *(const float4*)(g_O + (size_t)(m0 + srow + 64) * DIM + 4 * sc);
        stageA(&As[0][0], srow,      ra0);
        stageA(&As[0][0], srow + 64, ra1);
        asm volatile("cp.async.wait_group 0;");
        __syncthreads();
    }

    for (int kb = 0; kb < 64; kb++) {
        const int cur = kb & 1;
        const bool more = (kb + 1 < 64);
        if (more) {
            if (MODE == 1) issueA(cur ^ 1, kb + 1);
            issueB(cur ^ 1, kb + 1);
            CP_COMMIT();
            if (MODE == 0) {
                ra0 = *(const float4*)(g_O + (size_t)(m0 + srow)      * DIM + (kb + 1) * 16 + 4 * sc);
                ra1 = *(const float4*)(g_O + (size_t)(m0 + srow + 64) * DIM + (kb + 1) * 16 + 4 * sc);
            }
        }

        // fragment loads (one LDS.128 per row covers all 16 k)
        float4 fa[4][2], fb[4];
#pragma unroll
        for (int mt = 0; mt < 4; mt++) {
            int r = wy * 64 + mt * 16 + g;
            fa[mt][0] = *(float4*)&As[cur][r * 16 + 4 * (t ^ ((r >> 1) & 3))];
            int r2 = r + 8;
            fa[mt][1] = *(float4*)&As[cur][r2 * 16 + 4 * (t ^ ((r2 >> 1) & 3))];
        }
#pragma unroll
        for (int nt = 0; nt < 4; nt++) {
            int c = wx * 32 + nt * 8 + g;
            fb[nt] = *(float4*)&Bs[cur][c * 16 + 4 * (t ^ ((c >> 1) & 3))];
        }

#pragma unroll
        for (int mt = 0; mt < 4; mt++)
#pragma unroll
            for (int nt = 0; nt < 4; nt++) {
                mma8(acc[mt][nt], U(fa[mt][0].x), U(fa[mt][1].x),
                                  U(fa[mt][0].y), U(fa[mt][1].y),
                                  U(fb[nt].x),    U(fb[nt].y));
                mma8(acc[mt][nt], U(fa[mt][0].z), U(fa[mt][1].z),
                                  U(fa[mt][0].w), U(fa[mt][1].w),
                                  U(fb[nt].z),    U(fb[nt].w));
            }

        if (more) {
            if (MODE == 0) {
                stageA(&As[cur ^ 1][0], srow,      ra0);
                stageA(&As[cur ^ 1][0], srow + 64, ra1);
            }
            asm volatile("cp.async.wait_group 0;");
        }
        __syncthreads();
    }

    // epilogue
#pragma unroll
    for (int mt = 0; mt < 4; mt++) {
        int rbase = wy * 64 + mt * 16 + g;
#pragma unroll
        for (int nt = 0; nt < 4; nt++) {
            int cbase = wx * 32 + nt * 8 + 2 * t;
#pragma unroll
            for (int e = 0; e < 4; e++) {
                int gm = m0 + rbase + ((e >= 2) ? 8 : 0);
                int gn = n0 + cbase + (e & 1);
                float v = acc[mt][nt][e];
                if (MODE == 0) {
                    Cext[(size_t)gm * DIM + gn] = v + bias[gn];
                } else {
                    int bb = gm / SEQ, nrow = gm % SEQ;
                    int hh = gn / HDIM, hd = gn % HDIM;
                    float* dst = (sel == 0) ? g_Q : ((sel == 1) ? g_K : g_V);
                    dst[(((size_t)bb * NHEAD + hh) * SEQ + nrow) * HDIM + hd] = v;
                }
            }
        }
    }
}

// ---------------- fused causal attention with skewed relative positions ----------------
// srel[r,c] = q_{r-1} . e_{N-(r-c)} for c<r, 0 at c==r (via zero-filled E rows >= N).
// sQ/sK/sE: permuted 64-word rows. sVT: V transposed [hd][token] -> PV uses LDS.128.
// sE ring: 64 new rows staged per k-tile. P permuted into dead sQ region.
#define GBW 65
#define ATTN_SMEM_FLOATS (65*64 + 64*64 + 64*64 + 128*64 + 64*GBW)
#define ATTN_SMEM_BYTES  (ATTN_SMEM_FLOATS * 4)

__global__ __launch_bounds__(128, 2)
void attn_kernel(const float* __restrict__ rel)
{
    extern __shared__ float sm[];
    float* sQ  = sm;                    // [65][64] perm tf32; reused as P
    float* sK  = sQ + 65 * 64;          // [64][64] perm raw fp32
    float* sVT = sK + 64 * 64;          // [64][64] perm tf32, V^T
    float* sE  = sVT + 64 * 64;         // [128][64] perm raw fp32, ring
    float* sGb = sE + 128 * 64;         // [64][GBW] G band (scalar)
    float* sP  = sQ;

    const int qt = (gridDim.x - 1) - blockIdx.x;   // 31..0 (long CTAs first)
    const int bh = blockIdx.y;
    const int r0 = qt * 64;
    const int b  = bh / NHEAD;
    const int h  = bh % NHEAD;
    const int hcol = h * HDIM;

    const float* Qg = g_Q + (size_t)bh * SEQ * HDIM;
    const float* Kg = g_K + (size_t)bh * SEQ * HDIM;
    const float* Vg = g_V + (size_t)bh * SEQ * HDIM;

    const int tid = threadIdx.x;
    const int w = tid >> 5, lane = tid & 31, g = lane >> 2, t = lane & 3;
    const int rA = w * 16 + g;

    for (int idx = tid; idx < 65 * 16; idx += 128) {
        int row = idx >> 4, c4 = (idx & 15) << 2;
        int gr = r0 - 1 + row; if (gr < 0) gr = 0;
        float4 v = *(const float4*)(Qg + (size_t)gr * HDIM + c4);
        stash_perm(sQ + row * 64, c4,
                   make_float4(f2tf(v.x), f2tf(v.y), f2tf(v.z), f2tf(v.w)),
                   swz(row));
    }
    __syncthreads();

    uint32_t aQ[8][4], aQp[8][4];
#pragma unroll
    for (int kb = 0; kb < 4; kb++) {
        float4 f;
        f = frag4(sQ, 64, 1 + rA, kb, t);
        aQ[2*kb][0] = U(f.x); aQ[2*kb][2] = U(f.y);
        aQ[2*kb+1][0] = U(f.z); aQ[2*kb+1][2] = U(f.w);
        f = frag4(sQ, 64, 9 + rA, kb, t);
        aQ[2*kb][1] = U(f.x); aQ[2*kb][3] = U(f.y);
        aQ[2*kb+1][1] = U(f.z); aQ[2*kb+1][3] = U(f.w);
        f = frag4(sQ, 64, rA, kb, t);
        aQp[2*kb][0] = U(f.x); aQp[2*kb][2] = U(f.y);
        aQp[2*kb+1][0] = U(f.z); aQp[2*kb+1][2] = U(f.w);
        f = frag4(sQ, 64, 8 + rA, kb, t);
        aQp[2*kb][1] = U(f.x); aQp[2*kb][3] = U(f.y);
        aQp[2*kb+1][1] = U(f.z); aQp[2*kb+1][3] = U(f.w);
    }

    float Oacc[8][4];
#pragma unroll
    for (int i = 0; i < 8; i++)
#pragma unroll
        for (int e = 0; e < 4; e++) Oacc[i][e] = 0.f;
    float m0r = -1e30f, m1r = -1e30f;
    float l0r = 0.f,    l1r = 0.f;

    for (int j = 0; j <= qt; j++) {
        const int c0 = j * 64;
        const int ph = (j & 1) << 6;
        __syncthreads();

        for (int idx = tid; idx < 64 * 16; idx += 128) {
            int row = idx >> 4, c4 = (idx & 15) << 2;
            float4 kv = *(const float4*)(Kg + (size_t)(c0 + row) * HDIM + c4);
            stash_perm(sK + row * 64, c4, kv, swz(row));
        }
        for (int idx = tid; idx < 64 * 16; idx += 128) {
            int tok = idx & 63, c4 = (idx >> 6) << 2;
            float4 vv = *(const float4*)(Vg + (size_t)(c0 + tok) * HDIM + c4);
            float vals[4] = {f2tf(vv.x), f2tf(vv.y), f2tf(vv.z), f2tf(vv.w)};
            int chn = 4 * (tok >> 4) + (tok & 3);
            int wd  = (tok & 15) >> 2;
#pragma unroll
            for (int i = 0; i < 4; i++) {
                int r = c4 + i;
                sVT[r * 64 + 4 * (chn ^ swz(r)) + wd] = vals[i];
            }
        }
        const int elog0 = SEQ - r0 + c0 - 63;
        const int rbase = (j == 0) ? 0 : 64;
        for (int idx = tid; idx < (128 - rbase) * 16; idx += 128) {
            int row = rbase + (idx >> 4), c4 = (idx & 15) << 2;
            int el = elog0 + row;
            float4 ev = make_float4(0.f, 0.f, 0.f, 0.f);
            if (el < SEQ)
                ev = *(const float4*)(rel + (size_t)(el + (MAXLEN - SEQ)) * DIM + hcol + c4);
            int pr = row ^ ph;
            stash_perm(sE + pr * 64, c4, ev, swz(pr));
        }
        __syncthreads();

        const int nt0 = 6 - 2 * w;
#pragma unroll
        for (int ntl = 0; ntl < 10; ntl++) {
            const int nt = nt0 + ntl;
            float ga[4] = {0.f, 0.f, 0.f, 0.f};
            const int pr = (nt * 8 + g) ^ ph;
            float4 f0 = frag4(sE, 64, pr, 0, t);
            float4 f1 = frag4(sE, 64, pr, 1, t);
            float4 f2 = frag4(sE, 64, pr, 2, t);
            float4 f3 = frag4(sE, 64, pr, 3, t);
            mma8(ga, aQp[0][0], aQp[0][1], aQp[0][2], aQp[0][3], U(f0.x), U(f0.y));
            mma8(ga, aQp[1][0], aQp[1][1], aQp[1][2], aQp[1][3], U(f0.z), U(f0.w));
            mma8(ga, aQp[2][0], aQp[2][1], aQp[2][2], aQp[2][3], U(f1.x), U(f1.y));
            mma8(ga, aQp[3][0], aQp[3][1], aQp[3][2], aQp[3][3], U(f1.z), U(f1.w));
            mma8(ga, aQp[4][0], aQp[4][1], aQp[4][2], aQp[4][3], U(f2.x), U(f2.y));
            mma8(ga, aQp[5][0], aQp[5][1], aQp[5][2], aQp[5][3], U(f2.z), U(f2.w));
            mma8(ga, aQp[6][0], aQp[6][1], aQp[6][2], aQp[6][3], U(f3.x), U(f3.y));
            mma8(ga, aQp[7][0], aQp[7][1], aQp[7][2], aQp[7][3], U(f3.z), U(f3.w));
            const int cc = nt * 8 + 2 * t;
            const int i0 = cc + rA - 63;
            const int i2 = i0 + 8;
            if (i0 >= 0     && i0 < 64)     sGb[(rA)     * GBW + i0]     = ga[0];
            if (i0 + 1 >= 0 && i0 + 1 < 64) sGb[(rA)     * GBW + i0 + 1] = ga[1];
            if (i2 >= 0     && i2 < 64)     sGb[(rA + 8) * GBW + i2]     = ga[2];
            if (i2 + 1 >= 0 && i2 + 1 < 64) sGb[(rA + 8) * GBW + i2 + 1] = ga[3];
        }
        __syncwarp();

        float Sreg[8][4];
        float tmax0 = -1e30f, tmax1 = -1e30f;
#pragma unroll
        for (int nt = 0; nt < 8; nt++) {
            float* s = Sreg[nt];
            s[0] = s[1] = s[2] = s[3] = 0.f;
            const int kr = nt * 8 + g;
            float4 f0 = frag4(sK, 64, kr, 0, t);
            float4 f1 = frag4(sK, 64, kr, 1, t);
            float4 f2 = frag4(sK, 64, kr, 2, t);
            float4 f3 = frag4(sK, 64, kr, 3, t);
            mma8(s, aQ[0][0], aQ[0][1], aQ[0][2], aQ[0][3], U(f0.x), U(f0.y));
            mma8(s, aQ[1][0], aQ[1][1], aQ[1][2], aQ[1][3], U(f0.z), U(f0.w));
            mma8(s, aQ[2][0], aQ[2][1], aQ[2][2], aQ[2][3], U(f1.x), U(f1.y));
            mma8(s, aQ[3][0], aQ[3][1], aQ[3][2], aQ[3][3], U(f1.z), U(f1.w));
            mma8(s, aQ[4][0], aQ[4][1], aQ[4][2], aQ[4][3], U(f2.x), U(f2.y));
            mma8(s, aQ[5][0], aQ[5][1], aQ[5][2], aQ[5][3], U(f2.z), U(f2.w));
            mma8(s, aQ[6][0], aQ[6][1], aQ[6][2], aQ[6][3], U(f3.x), U(f3.y));
            mma8(s, aQ[7][0], aQ[7][1], aQ[7][2], aQ[7][3], U(f3.z), U(f3.w));

            const int cc0 = nt * 8 + 2 * t;
            float v;
            v = (s[0] + sGb[rA * GBW + cc0]) * 0.125f;
            if (c0 + cc0 > r0 + rA) v = -1e30f;
            s[0] = v; tmax0 = fmaxf(tmax0, v);

            v = (s[1] + sGb[rA * GBW + cc0 + 1]) * 0.125f;
            if (c0 + cc0 + 1 > r0 + rA) v = -1e30f;
            s[1] = v; tmax0 = fmaxf(tmax0, v);

            v = (s[2] + sGb[(rA + 8) * GBW + cc0]) * 0.125f;
            if (c0 + cc0 > r0 + rA + 8) v = -1e30f;
            s[2] = v; tmax1 = fmaxf(tmax1, v);

            v = (s[3] + sGb[(rA + 8) * GBW + cc0 + 1]) * 0.125f;
            if (c0 + cc0 + 1 > r0 + rA + 8) v = -1e30f;
            s[3] = v; tmax1 = fmaxf(tmax1, v);
        }

        tmax0 = fmaxf(tmax0, __shfl_xor_sync(0xffffffffu, tmax0, 1));
        tmax0 = fmaxf(tmax0, __shfl_xor_sync(0xffffffffu, tmax0, 2));
        tmax1 = fmaxf(tmax1, __shfl_xor_sync(0xffffffffu, tmax1, 1));
        tmax1 = fmaxf(tmax1, __shfl_xor_sync(0xffffffffu, tmax1, 2));

        float mn0 = fmaxf(m0r, tmax0), mn1 = fmaxf(m1r, tmax1);
        float f0s = __expf(m0r - mn0), f1s = __expf(m1r - mn1);
        float rs0 = 0.f, rs1 = 0.f;
#pragma unroll
        for (int nt = 0; nt < 8; nt++) {
            float* s = Sreg[nt];
            s[0] = __expf(s[0] - mn0); s[1] = __expf(s[1] - mn0);
            s[2] = __expf(s[2] - mn1); s[3] = __expf(s[3] - mn1);
            rs0 += s[0] + s[1];
            rs1 += s[2] + s[3];
        }
        rs0 += __shfl_xor_sync(0xffffffffu, rs0, 1);
        rs0 += __shfl_xor_sync(0xffffffffu, rs0, 2);
        rs1 += __shfl_xor_sync(0xffffffffu, rs1, 1);
        rs1 += __shfl_xor_sync(0xffffffffu, rs1, 2);

        m0r = mn0; m1r = mn1;
        l0r = l0r * f0s + rs0;
        l1r = l1r * f1s + rs1;
#pragma unroll
        for (int dn = 0; dn < 8; dn++) {
            Oacc[dn][0] *= f0s; Oacc[dn][1] *= f0s;
            Oacc[dn][2] *= f1s; Oacc[dn][3] *= f1s;
        }

        __syncwarp();
#pragma unroll
        for (int nt = 0; nt < 8; nt++) {
            int c = nt * 8 + 2 * t;
            int ch = 4 * (c >> 4) + (c & 3);
            int wd = (c & 15) >> 2;
            int s0 = swz(rA), s1 = swz(rA + 8);
            sP[(rA)     * 64 + 4 * ((ch)     ^ s0) + wd] = f2tf(Sreg[nt][0]);
            sP[(rA)     * 64 + 4 * ((ch + 1) ^ s0) + wd] = f2tf(Sreg[nt][1]);
            sP[(rA + 8) * 64 + 4 * ((ch)     ^ s1) + wd] = f2tf(Sreg[nt][2]);
            sP[(rA + 8) * 64 + 4 * ((ch + 1) ^ s1) + wd] = f2tf(Sreg[nt][3]);
        }
        __syncwarp();

        uint32_t aP[8][4];
#pragma unroll
        for (int kb = 0; kb < 4; kb++) {
            float4 f;
            f = frag4(sP, 64, rA, kb, t);
            aP[2*kb][0] = U(f.x); aP[2*kb][2] = U(f.y);
            aP[2*kb+1][0] = U(f.z); aP[2*kb+1][2] = U(f.w);
            f = frag4(sP, 64, rA + 8, kb, t);
            aP[2*kb][1] = U(f.x); aP[2*kb][3] = U(f.y);
            aP[2*kb+1][1] = U(f.z); aP[2*kb+1][3] = U(f.w);
        }

#pragma unroll
        for (int dn = 0; dn < 8; dn++) {
            const int nb = dn * 8 + g;
            float4 v0 = frag4(sVT, 64, nb, 0, t);
            float4 v1 = frag4(sVT, 64, nb, 1, t);
            float4 v2 = frag4(sVT, 64, nb, 2, t);
            float4 v3 = frag4(sVT, 64, nb, 3, t);
            mma8(Oacc[dn], aP[0][0], aP[0][1], aP[0][2], aP[0][3], U(v0.x), U(v0.y));
            mma8(Oacc[dn], aP[1][0], aP[1][1], aP[1][2], aP[1][3], U(v0.z), U(v0.w));
            mma8(Oacc[dn], aP[2][0], aP[2][1], aP[2][2], aP[2][3], U(v1.x), U(v1.y));
            mma8(Oacc[dn], aP[3][0], aP[3][1], aP[3][2], aP[3][3], U(v1.z), U(v1.w));
            mma8(Oacc[dn], aP[4][0], aP[4][1], aP[4][2], aP[4][3], U(v2.x), U(v2.y));
            mma8(Oacc[dn], aP[5][0], aP[5][1], aP[5][2], aP[5][3], U(v2.z), U(v2.w));
            mma8(Oacc[dn], aP[6][0], aP[6][1], aP[6][2], aP[6][3], U(v3.x), U(v3.y));
            mma8(Oacc[dn], aP[7][0], aP[7][1], aP[7][2], aP[7][3], U(v3.z), U(v3.w));
        }
    }

    float inv0 = 1.f / l0r, inv1 = 1.f / l1r;
    float* Og = g_O + (size_t)b * SEQ * DIM + (size_t)r0 * DIM + hcol;
#pragma unroll
    for (int dn = 0; dn < 8; dn++) {
        int d0 = dn * 8 + 2 * t;
        Og[(size_t)(rA)     * DIM + d0]     = Oacc[dn][0] * inv0;
        Og[(size_t)(rA)     * DIM + d0 + 1] = Oacc[dn][1] * inv0;
        Og[(size_t)(rA + 8) * DIM + d0]     = Oacc[dn][2] * inv1;
        Og[(size_t)(rA + 8) * DIM + d0 + 1] = Oacc[dn][3] * inv1;
    }
}

// ---------------- launch ----------------
extern "C" void kernel_launch(void* const* d_in, const int* in_sizes, int n_in,
                              void* d_out, int out_size)
{
    const float* x   = (const float*)d_in[0];
    const float* Wq  = (const float*)d_in[1];
    const float* Wk  = (const float*)d_in[2];
    const float* Wv  = (const float*)d_in[3];
    const float* Wp  = (const float*)d_in[4];
    const float* bp  = (const float*)d_in[5];
    const float* rel = (const float*)d_in[6];
    float* out = (float*)d_out;

    cudaFuncSetAttribute(attn_kernel,
                         cudaFuncAttributeMaxDynamicSharedMemorySize,
                         ATTN_SMEM_BYTES);

    float *d_xp, *d_Wqp, *d_Wkp, *d_Wvp, *d_Wpp;
    cudaGetSymbolAddress((void**)&d_xp,  g_xp);
    cudaGetSymbolAddress((void**)&d_Wqp, g_Wqp);
    cudaGetSymbolAddress((void**)&d_Wkp, g_Wkp);
    cudaGetSymbolAddress((void**)&d_Wvp, g_Wvp);
    cudaGetSymbolAddress((void**)&d_Wpp, g_Wpp);

    const int ngx = BN * DIM / 16;      // 262144 groups
    const int ngw = DIM * DIM / 16;     // 65536 groups
    permute_cvt<<<(ngx + 255) / 256, 256>>>(x,  d_xp,  ngx);
    permute_cvt<<<(ngw + 255) / 256, 256>>>(Wq, d_Wqp, ngw);
    permute_cvt<<<(ngw + 255) / 256, 256>>>(Wk, d_Wkp, ngw);
    permute_cvt<<<(ngw + 255) / 256, 256>>>(Wv, d_Wvp, ngw);
    permute_cvt<<<(ngw + 255) / 256, 256>>>(Wp, d_Wpp, ngw);

    gemm_tn<1><<<dim3(DIM / 128, BN / 128, 3), 256>>>(d_Wqp, d_Wkp, d_Wvp, nullptr, nullptr);
    attn_kernel<<<dim3(SEQ / 64, BATCH * NHEAD), 128, ATTN_SMEM_BYTES>>>(rel);
    gemm_tn<0><<<dim3(DIM / 128, BN / 128), 256>>>(d_Wpp, nullptr, nullptr, bp, out);
}

// round 16
// speedup vs baseline: 2.0650x; 1.3557x over previous
#include <cuda_runtime.h>
#include <stdint.h>

#define BATCH   2
#define SEQ     2048
#define DIM     1024
#define NHEAD   16
#define HDIM    64
#define MAXLEN  2048
#define BN      (BATCH*SEQ)
#define EROWS   (SEQ + 128)

// ---------------- scratch (device globals; allocation is forbidden) ----------------
__device__ float g_Q  [(size_t)BATCH * NHEAD * SEQ * HDIM];  // linear [(bh)][n][hd]
__device__ float g_Kp [(size_t)BATCH * NHEAD * SEQ * HDIM];  // smem-image per (bh,tile)
__device__ float g_VTp[(size_t)BATCH * NHEAD * SEQ * HDIM];  // transposed smem-image, tf32
__device__ float g_O  [(size_t)BATCH * SEQ * DIM];           // raw fp32
__device__ float g_Ep [(size_t)NHEAD * EROWS * HDIM];        // per-head permuted E, zero-padded
// permuted + RNA-tf32 copies in the exact gemm smem image layout
__device__ float g_xp [(size_t)BN * DIM];
__device__ float g_Wqp[(size_t)DIM * DIM];
__device__ float g_Wkp[(size_t)DIM * DIM];
__device__ float g_Wvp[(size_t)DIM * DIM];
__device__ float g_Wpp[(size_t)DIM * DIM];

// ---------------- helpers ----------------
__device__ __forceinline__ uint32_t f2t(float f) {
    uint32_t u;
    asm("cvt.rna.tf32.f32 %0, %1;" : "=r"(u) : "f"(f));
    return u;
}
__device__ __forceinline__ float f2tf(float f) {
    return __uint_as_float(f2t(f));
}
__device__ __forceinline__ void mma8(float c[4],
                                     uint32_t a0, uint32_t a1, uint32_t a2, uint32_t a3,
                                     uint32_t b0, uint32_t b1) {
    asm volatile(
        "mma.sync.aligned.m16n8k8.row.col.f32.tf32.tf32.f32 "
        "{%0,%1,%2,%3},{%4,%5,%6,%7},{%8,%9},{%0,%1,%2,%3};"
        : "+f"(c[0]), "+f"(c[1]), "+f"(c[2]), "+f"(c[3])
        : "r"(a0), "r"(a1), "r"(a2), "r"(a3), "r"(b0), "r"(b1));
}
#define U(x) __float_as_uint(x)

__device__ __forceinline__ void cp16(uint32_t saddr, const float* gptr) {
    asm volatile("cp.async.cg.shared.global [%0], [%1], 16;" :: "r"(saddr), "l"(gptr));
}
#define CP_COMMIT() asm volatile("cp.async.commit_group;")
#define CP_WAIT0()  asm volatile("cp.async.wait_group 0;")

// chunk swizzle for 64-word permuted rows (uses row bits 0..2 only)
__device__ __forceinline__ int swz(int row) {
    return ((row & 1) << 2) | ((row >> 1) & 3);
}
// word index of element k within a permuted 64-word row
__device__ __forceinline__ int pword(int k, int row) {
    return 4 * ((4 * (k >> 4) + (k & 3)) ^ swz(row)) + ((k & 15) >> 2);
}
__device__ __forceinline__ void stash_perm(float* rowp, int c4, float4 v, int s) {
    int a4 = 4 * (c4 >> 4);
    int wd = (c4 & 15) >> 2;
    rowp[4 * ((a4 + 0) ^ s) + wd] = v.x;
    rowp[4 * ((a4 + 1) ^ s) + wd] = v.y;
    rowp[4 * ((a4 + 2) ^ s) + wd] = v.z;
    rowp[4 * ((a4 + 3) ^ s) + wd] = v.w;
}
__device__ __forceinline__ float4 frag4(const float* S, int stride, int row, int kb, int t) {
    return *(const float4*)&S[row * stride + 4 * ((4 * kb + t) ^ swz(row))];
}

// ---------------- prologue kernels ----------------
// permute + RNA-cvt x/W into the gemm smem image (1024-wide rows, 16-word groups)
__global__ void permute_cvt(const float* __restrict__ src, float* __restrict__ dst,
                            int ngroups)
{
    int gi = blockIdx.x * 256 + threadIdx.x;
    if (gi >= ngroups) return;
    int row = gi >> 6;
    int sxb = (row >> 1) & 3;
    const float4* s = (const float4*)(src + (size_t)gi * 16);
    float4 v0 = s[0], v1 = s[1], v2 = s[2], v3 = s[3];
    float4* d = (float4*)(dst + (size_t)gi * 16);
    d[0 ^ sxb] = make_float4(f2tf(v0.x), f2tf(v1.x), f2tf(v2.x), f2tf(v3.x));
    d[1 ^ sxb] = make_float4(f2tf(v0.y), f2tf(v1.y), f2tf(v2.y), f2tf(v3.y));
    d[2 ^ sxb] = make_float4(f2tf(v0.z), f2tf(v1.z), f2tf(v2.z), f2tf(v3.z));
    d[3 ^ sxb] = make_float4(f2tf(v0.w), f2tf(v1.w), f2tf(v2.w), f2tf(v3.w));
}

// E per head: g_Ep[h][L][pword(k, L&127)] = rel[(L + MAXLEN-SEQ)*DIM + h*64 + k], 0 for L>=SEQ
__global__ void permute_E(const float* __restrict__ rel)
{
    int task = blockIdx.x * 256 + threadIdx.x;      // (h, L, grp) grp in 0..15
    if (task >= NHEAD * EROWS * 16) return;
    int grp = task & 15;
    int L   = (task >> 4) % EROWS;
    int h   = task / (16 * EROWS);
    float4 v = make_float4(0.f, 0.f, 0.f, 0.f);
    if (L < SEQ)
        v = *(const float4*)(rel + (size_t)(L + (MAXLEN - SEQ)) * DIM + h * HDIM + grp * 4);
    stash_perm(g_Ep + ((size_t)h * EROWS + L) * 64, grp * 4, v, swz(L & 127));
}

// ---------------- GEMM: C[m,n] = sum_k A[m,k] * W[n,k], 1x tf32 ----------------
// MODE 1: A = g_xp (cp.async), B = W{q,k,v}p by blockIdx.z (cp.async); writes Q/Kp/VTp.
// MODE 0: A = g_O raw (LDG+cvt+STS), B = g_Wpp (cp.async); C = out + bias.
template<int MODE>
__global__ __launch_bounds__(256, 2)
void gemm_tn(const float* __restrict__ B0, const float* __restrict__ B1,
             const float* __restrict__ B2,
             const float* __restrict__ bias, float* __restrict__ Cext)
{
    __align__(16) __shared__ float As[2][128 * 16];
    __align__(16) __shared__ float Bs[2][128 * 16];

    const int sel = (MODE == 1) ? blockIdx.z : 0;
    const float* Bp = (sel == 0) ? B0 : ((sel == 1) ? B1 : B2);

    const int m0 = blockIdx.y * 128;
    const int n0 = blockIdx.x * 128;
    const int tid = threadIdx.x;
    const int w = tid >> 5, lane = tid & 31, g = lane >> 2, t = lane & 3;
    const int wy = w >> 2, wx = w & 3;   // 2x4 warp grid; warp tile 64x32

    const uint32_t sA = (uint32_t)__cvta_generic_to_shared(&As[0][0]);
    const uint32_t sB = (uint32_t)__cvta_generic_to_shared(&Bs[0][0]);

    const int srow = tid >> 2;
    const int sc   = tid & 3;
    const int sxb  = (srow >> 1) & 3;
    auto stageA = [&](float* S, int row, float4 v) {
        float* base = S + row * 16 + sc;
        base[4 * (0 ^ sxb)] = f2tf(v.x);
        base[4 * (1 ^ sxb)] = f2tf(v.y);
        base[4 * (2 ^ sxb)] = f2tf(v.z);
        base[4 * (3 ^ sxb)] = f2tf(v.w);
    };

    auto issueB = [&](int buf, int kb) {
#pragma unroll
        for (int r = 0; r < 2; r++) {
            int ch = tid + 256 * r;
            int row = ch >> 2, wg = ch & 3;
            cp16(sB + (uint32_t)(buf * 2048 + 4 * ch) * 4,
                 Bp + (size_t)(n0 + row) * DIM + kb * 16 + wg * 4);
        }
    };
    auto issueA = [&](int buf, int kb) {
#pragma unroll
        for (int r = 0; r < 2; r++) {
            int ch = tid + 256 * r;
            int row = ch >> 2, wg = ch & 3;
            cp16(sA + (uint32_t)(buf * 2048 + 4 * ch) * 4,
                 g_xp + (size_t)(m0 + row) * DIM + kb * 16 + wg * 4);
        }
    };

    float acc[4][4][4];
#pragma unroll
    for (int i = 0; i < 4; i++)
#pragma unroll
        for (int j = 0; j < 4; j++)
#pragma unroll
            for (int e = 0; e < 4; e++) acc[i][j][e] = 0.f;

    float4 ra0, ra1;
    if (MODE == 1) {
        issueA(0, 0);
        issueB(0, 0);
        CP_COMMIT();
        CP_WAIT0();
        __syncthreads();
    } else {
        issueB(0, 0);
        CP_COMMIT();
        ra0 = *(const float4*)(g_O + (size_t)(m0 + srow)      * DIM + 4 * sc);
        ra1 = *(const float4*)(g_O + (size_t)(m0 + srow + 64) * DIM + 4 * sc);
        stageA(&As[0][0], srow,      ra0);
        stageA(&As[0][0], srow + 64, ra1);
        CP_WAIT0();
        __syncthreads();
    }

    for (int kb = 0; kb < 64; kb++) {
        const int cur = kb & 1;
        const bool more = (kb + 1 < 64);
        if (more) {
            if (MODE == 1) issueA(cur ^ 1, kb + 1);
            issueB(cur ^ 1, kb + 1);
            CP_COMMIT();
            if (MODE == 0) {
                ra0 = *(const float4*)(g_O + (size_t)(m0 + srow)      * DIM + (kb + 1) * 16 + 4 * sc);
                ra1 = *(const float4*)(g_O + (size_t)(m0 + srow + 64) * DIM + (kb + 1) * 16 + 4 * sc);
            }
        }

        float4 fa[4][2], fb[4];
#pragma unroll
        for (int mt = 0; mt < 4; mt++) {
            int r = wy * 64 + mt * 16 + g;
            fa[mt][0] = *(float4*)&As[cur][r * 16 + 4 * (t ^ ((r >> 1) & 3))];
            int r2 = r + 8;
            fa[mt][1] = *(float4*)&As[cur][r2 * 16 + 4 * (t ^ ((r2 >> 1) & 3))];
        }
#pragma unroll
        for (int nt = 0; nt < 4; nt++) {
            int c = wx * 32 + nt * 8 + g;
            fb[nt] = *(float4*)&Bs[cur][c * 16 + 4 * (t ^ ((c >> 1) & 3))];
        }

#pragma unroll
        for (int mt = 0; mt < 4; mt++)
#pragma unroll
            for (int nt = 0; nt < 4; nt++) {
                mma8(acc[mt][nt], U(fa[mt][0].x), U(fa[mt][1].x),
                                  U(fa[mt][0].y), U(fa[mt][1].y),
                                  U(fb[nt].x),    U(fb[nt].y));
                mma8(acc[mt][nt], U(fa[mt][0].z), U(fa[mt][1].z),
                                  U(fa[mt][0].w), U(fa[mt][1].w),
                                  U(fb[nt].z),    U(fb[nt].w));
            }

        if (more) {
            if (MODE == 0) {
                stageA(&As[cur ^ 1][0], srow,      ra0);
                stageA(&As[cur ^ 1][0], srow + 64, ra1);
            }
            CP_WAIT0();
        }
        __syncthreads();
    }

    // epilogue
#pragma unroll
    for (int mt = 0; mt < 4; mt++) {
        int rbase = wy * 64 + mt * 16 + g;
#pragma unroll
        for (int nt = 0; nt < 4; nt++) {
            int cbase = wx * 32 + nt * 8 + 2 * t;
#pragma unroll
            for (int e = 0; e < 4; e++) {
                int gm = m0 + rbase + ((e >= 2) ? 8 : 0);
                int gn = n0 + cbase + (e & 1);
                float v = acc[mt][nt][e];
                if (MODE == 0) {
                    Cext[(size_t)gm * DIM + gn] = v + bias[gn];
                } else {
                    int bb = gm / SEQ, nrow = gm % SEQ;
                    int hh = gn / HDIM, hd = gn % HDIM;
                    int bh = bb * NHEAD + hh;
                    int tile = nrow >> 6, tok = nrow & 63;
                    if (sel == 0) {
                        g_Q[((size_t)bh * SEQ + nrow) * HDIM + hd] = v;
                    } else if (sel == 1) {
                        g_Kp[(((size_t)bh * 32 + tile) * 64 + tok) * 64 + pword(hd, tok)] = v;
                    } else {
                        g_VTp[(((size_t)bh * 32 + tile) * 64 + hd) * 64 + pword(tok, hd)] = f2tf(v);
                    }
                }
            }
        }
    }
}

// ---------------- fused causal attention with skewed relative positions ----------------
// srel[r,c] = q_{r-1} . e_{N-(r-c)} for c<r, 0 at c==r (zero-padded E rows >= N).
// K/V^T/E staged by pure cp.async block copies (layouts prebuilt in global memory).
// E ring slot = L & 127 (swizzle depends only on row bits 0..2 -> consistent).
#define GBW 65
#define ATTN_SMEM_FLOATS (65*64 + 64*64 + 64*64 + 128*64 + 64*GBW)
#define ATTN_SMEM_BYTES  (ATTN_SMEM_FLOATS * 4)
#define SCL (0.125f * 1.44269504088896f)   // 1/sqrt(64) * log2(e); softmax via exp2

__global__ __launch_bounds__(128, 2)
void attn_kernel()
{
    extern __shared__ float sm[];
    float* sQ  = sm;                    // [65][64] perm tf32; reused as P
    float* sK  = sQ + 65 * 64;          // [64][64] smem image (cp.async)
    float* sVT = sK + 64 * 64;          // [64][64] V^T image, tf32 (cp.async)
    float* sE  = sVT + 64 * 64;         // [128][64] E ring, slot = L&127 (cp.async)
    float* sGb = sE + 128 * 64;         // [64][GBW] G band (scalar)
    float* sP  = sQ;

    const uint32_t aK  = (uint32_t)__cvta_generic_to_shared(sK);
    const uint32_t aVT = (uint32_t)__cvta_generic_to_shared(sVT);
    const uint32_t aE  = (uint32_t)__cvta_generic_to_shared(sE);

    const int qt = (gridDim.x - 1) - blockIdx.x;   // 31..0 (long CTAs first)
    const int bh = blockIdx.y;
    const int r0 = qt * 64;
    const int b  = bh / NHEAD;
    const int h  = bh % NHEAD;
    const int hcol = h * HDIM;

    const float* Qg  = g_Q   + (size_t)bh * SEQ * HDIM;
    const float* Kpg = g_Kp  + (size_t)bh * 32 * 4096;
    const float* VTg = g_VTp + (size_t)bh * 32 * 4096;
    const float* Epg = g_Ep  + (size_t)h * EROWS * 64;

    const int tid = threadIdx.x;
    const int w = tid >> 5, lane = tid & 31, g = lane >> 2, t = lane & 3;
    const int rA = w * 16 + g;

    for (int idx = tid; idx < 65 * 16; idx += 128) {
        int row = idx >> 4, c4 = (idx & 15) << 2;
        int gr = r0 - 1 + row; if (gr < 0) gr = 0;
        float4 v = *(const float4*)(Qg + (size_t)gr * HDIM + c4);
        stash_perm(sQ + row * 64, c4,
                   make_float4(f2tf(v.x), f2tf(v.y), f2tf(v.z), f2tf(v.w)),
                   swz(row));
    }
    __syncthreads();

    uint32_t aQ[8][4], aQp[8][4];
#pragma unroll
    for (int kb = 0; kb < 4; kb++) {
        float4 f;
        f = frag4(sQ, 64, 1 + rA, kb, t);
        aQ[2*kb][0] = U(f.x); aQ[2*kb][2] = U(f.y);
        aQ[2*kb+1][0] = U(f.z); aQ[2*kb+1][2] = U(f.w);
        f = frag4(sQ, 64, 9 + rA, kb, t);
        aQ[2*kb][1] = U(f.x); aQ[2*kb][3] = U(f.y);
        aQ[2*kb+1][1] = U(f.z); aQ[2*kb+1][3] = U(f.w);
        f = frag4(sQ, 64, rA, kb, t);
        aQp[2*kb][0] = U(f.x); aQp[2*kb][2] = U(f.y);
        aQp[2*kb+1][0] = U(f.z); aQp[2*kb+1][2] = U(f.w);
        f = frag4(sQ, 64, 8 + rA, kb, t);
        aQp[2*kb][1] = U(f.x); aQp[2*kb][3] = U(f.y);
        aQp[2*kb+1][1] = U(f.z); aQp[2*kb+1][3] = U(f.w);
    }

    float Oacc[8][4];
#pragma unroll
    for (int i = 0; i < 8; i++)
#pragma unroll
        for (int e = 0; e < 4; e++) Oacc[i][e] = 0.f;
    float m0r = -1e30f, m1r = -1e30f;
    float l0r = 0.f,    l1r = 0.f;

    for (int j = 0; j <= qt; j++) {
        const int c0 = j * 64;
        const int elog0 = SEQ - r0 + c0 - 63;   // >= 1 always
        __syncthreads();   // previous iteration's smem readers done

        // ---- cp.async staging: K, V^T (block copies), E ring ----
#pragma unroll
        for (int r = 0; r < 8; r++) {
            int ch = tid + 128 * r;             // 1024 chunks of 16B
            cp16(aK  + (uint32_t)ch * 16, Kpg + (size_t)j * 4096 + ch * 4);
            cp16(aVT + (uint32_t)ch * 16, VTg + (size_t)j * 4096 + ch * 4);
        }
        if (j == 0) {
#pragma unroll
            for (int r = 0; r < 16; r++) {
                int ch = tid + 128 * r;         // 2048 chunks: rows 0..127
                int er = ch >> 4, cw = ch & 15;
                int L = elog0 + er;
                cp16(aE + (uint32_t)(((L & 127) * 64 + cw * 4)) * 4,
                     Epg + (size_t)L * 64 + cw * 4);
            }
        } else {
#pragma unroll
            for (int r = 0; r < 8; r++) {
                int ch = tid + 128 * r;         // 1024 chunks: rows 64..127
                int er = 64 + (ch >> 4), cw = ch & 15;
                int L = elog0 + er;
                cp16(aE + (uint32_t)(((L & 127) * 64 + cw * 4)) * 4,
                     Epg + (size_t)L * 64 + cw * 4);
            }
        }
        CP_COMMIT();
        CP_WAIT0();
        __syncthreads();

        // ---- G band = Qprev @ Ewin^T (warp-trimmed n-tiles) ----
        const int nt0 = 6 - 2 * w;
#pragma unroll
        for (int ntl = 0; ntl < 10; ntl++) {
            const int nt = nt0 + ntl;
            float ga[4] = {0.f, 0.f, 0.f, 0.f};
            const int slot = (elog0 + nt * 8 + g) & 127;
            float4 f0 = frag4(sE, 64, slot, 0, t);
            float4 f1 = frag4(sE, 64, slot, 1, t);
            float4 f2 = frag4(sE, 64, slot, 2, t);
            float4 f3 = frag4(sE, 64, slot, 3, t);
            mma8(ga, aQp[0][0], aQp[0][1], aQp[0][2], aQp[0][3], U(f0.x), U(f0.y));
            mma8(ga, aQp[1][0], aQp[1][1], aQp[1][2], aQp[1][3], U(f0.z), U(f0.w));
            mma8(ga, aQp[2][0], aQp[2][1], aQp[2][2], aQp[2][3], U(f1.x), U(f1.y));
            mma8(ga, aQp[3][0], aQp[3][1], aQp[3][2], aQp[3][3], U(f1.z), U(f1.w));
            mma8(ga, aQp[4][0], aQp[4][1], aQp[4][2], aQp[4][3], U(f2.x), U(f2.y));
            mma8(ga, aQp[5][0], aQp[5][1], aQp[5][2], aQp[5][3], U(f2.z), U(f2.w));
            mma8(ga, aQp[6][0], aQp[6][1], aQp[6][2], aQp[6][3], U(f3.x), U(f3.y));
            mma8(ga, aQp[7][0], aQp[7][1], aQp[7][2], aQp[7][3], U(f3.z), U(f3.w));
            const int cc = nt * 8 + 2 * t;
            const int i0 = cc + rA - 63;
            const int i2 = i0 + 8;
            if (i0 >= 0     && i0 < 64)     sGb[(rA)     * GBW + i0]     = ga[0];
            if (i0 + 1 >= 0 && i0 + 1 < 64) sGb[(rA)     * GBW + i0 + 1] = ga[1];
            if (i2 >= 0     && i2 < 64)     sGb[(rA + 8) * GBW + i2]     = ga[2];
            if (i2 + 1 >= 0 && i2 + 1 < 64) sGb[(rA + 8) * GBW + i2 + 1] = ga[3];
        }
        __syncwarp();

        // ---- S = Q @ K^T + srel (band gather), mask, scale (pre-folded log2e) ----
        float Sreg[8][4];
        float tmax0 = -1e30f, tmax1 = -1e30f;
#pragma unroll
        for (int nt = 0; nt < 8; nt++) {
            float* s = Sreg[nt];
            s[0] = s[1] = s[2] = s[3] = 0.f;
            const int kr = nt * 8 + g;
            float4 f0 = frag4(sK, 64, kr, 0, t);
            float4 f1 = frag4(sK, 64, kr, 1, t);
            float4 f2 = frag4(sK, 64, kr, 2, t);
            float4 f3 = frag4(sK, 64, kr, 3, t);
            mma8(s, aQ[0][0], aQ[0][1], aQ[0][2], aQ[0][3], U(f0.x), U(f0.y));
            mma8(s, aQ[1][0], aQ[1][1], aQ[1][2], aQ[1][3], U(f0.z), U(f0.w));
            mma8(s, aQ[2][0], aQ[2][1], aQ[2][2], aQ[2][3], U(f1.x), U(f1.y));
            mma8(s, aQ[3][0], aQ[3][1], aQ[3][2], aQ[3][3], U(f1.z), U(f1.w));
            mma8(s, aQ[4][0], aQ[4][1], aQ[4][2], aQ[4][3], U(f2.x), U(f2.y));
            mma8(s, aQ[5][0], aQ[5][1], aQ[5][2], aQ[5][3], U(f2.z), U(f2.w));
            mma8(s, aQ[6][0], aQ[6][1], aQ[6][2], aQ[6][3], U(f3.x), U(f3.y));
            mma8(s, aQ[7][0], aQ[7][1], aQ[7][2], aQ[7][3], U(f3.z), U(f3.w));

            const int cc0 = nt * 8 + 2 * t;
            float v;
            v = (s[0] + sGb[rA * GBW + cc0]) * SCL;
            if (c0 + cc0 > r0 + rA) v = -1e30f;
            s[0] = v; tmax0 = fmaxf(tmax0, v);

            v = (s[1] + sGb[rA * GBW + cc0 + 1]) * SCL;
            if (c0 + cc0 + 1 > r0 + rA) v = -1e30f;
            s[1] = v; tmax0 = fmaxf(tmax0, v);

            v = (s[2] + sGb[(rA + 8) * GBW + cc0]) * SCL;
            if (c0 + cc0 > r0 + rA + 8) v = -1e30f;
            s[2] = v; tmax1 = fmaxf(tmax1, v);

            v = (s[3] + sGb[(rA + 8) * GBW + cc0 + 1]) * SCL;
            if (c0 + cc0 + 1 > r0 + rA + 8) v = -1e30f;
            s[3] = v; tmax1 = fmaxf(tmax1, v);
        }

        tmax0 = fmaxf(tmax0, __shfl_xor_sync(0xffffffffu, tmax0, 1));
        tmax0 = fmaxf(tmax0, __shfl_xor_sync(0xffffffffu, tmax0, 2));
        tmax1 = fmaxf(tmax1, __shfl_xor_sync(0xffffffffu, tmax1, 1));
        tmax1 = fmaxf(tmax1, __shfl_xor_sync(0xffffffffu, tmax1, 2));

        float mn0 = fmaxf(m0r, tmax0), mn1 = fmaxf(m1r, tmax1);
        float f0s = exp2f(m0r - mn0), f1s = exp2f(m1r - mn1);
        float rs0 = 0.f, rs1 = 0.f;
#pragma unroll
        for (int nt = 0; nt < 8; nt++) {
            float* s = Sreg[nt];
            s[0] = exp2f(s[0] - mn0); s[1] = exp2f(s[1] - mn0);
            s[2] = exp2f(s[2] - mn1); s[3] = exp2f(s[3] - mn1);
            rs0 += s[0] + s[1];
            rs1 += s[2] + s[3];
        }
        rs0 += __shfl_xor_sync(0xffffffffu, rs0, 1);
        rs0 += __shfl_xor_sync(0xffffffffu, rs0, 2);
        rs1 += __shfl_xor_sync(0xffffffffu, rs1, 1);
        rs1 += __shfl_xor_sync(0xffffffffu, rs1, 2);

        m0r = mn0; m1r = mn1;
        l0r = l0r * f0s + rs0;
        l1r = l1r * f1s + rs1;
#pragma unroll
        for (int dn = 0; dn < 8; dn++) {
            Oacc[dn][0] *= f0s; Oacc[dn][1] *= f0s;
            Oacc[dn][2] *= f1s; Oacc[dn][3] *= f1s;
        }

        __syncwarp();
#pragma unroll
        for (int nt = 0; nt < 8; nt++) {
            int c = nt * 8 + 2 * t;
            int ch = 4 * (c >> 4) + (c & 3);
            int wd = (c & 15) >> 2;
            int s0 = swz(rA), s1 = swz(rA + 8);
            sP[(rA)     * 64 + 4 * ((ch)     ^ s0) + wd] = f2tf(Sreg[nt][0]);
            sP[(rA)     * 64 + 4 * ((ch + 1) ^ s0) + wd] = f2tf(Sreg[nt][1]);
            sP[(rA + 8) * 64 + 4 * ((ch)     ^ s1) + wd] = f2tf(Sreg[nt][2]);
            sP[(rA + 8) * 64 + 4 * ((ch + 1) ^ s1) + wd] = f2tf(Sreg[nt][3]);
        }
        __syncwarp();

        uint32_t aP[8][4];
#pragma unroll
        for (int kb = 0; kb < 4; kb++) {
            float4 f;
            f = frag4(sP, 64, rA, kb, t);
            aP[2*kb][0] = U(f.x); aP[2*kb][2] = U(f.y);
            aP[2*kb+1][0] = U(f.z); aP[2*kb+1][2] = U(f.w);
            f = frag4(sP, 64, rA + 8, kb, t);
            aP[2*kb][1] = U(f.x); aP[2*kb][3] = U(f.y);
            aP[2*kb+1][1] = U(f.z); aP[2*kb+1][3] = U(f.w);
        }

#pragma unroll
        for (int dn = 0; dn < 8; dn++) {
            const int nb = dn * 8 + g;
            float4 v0 = frag4(sVT, 64, nb, 0, t);
            float4 v1 = frag4(sVT, 64, nb, 1, t);
            float4 v2 = frag4(sVT, 64, nb, 2, t);
            float4 v3 = frag4(sVT, 64, nb, 3, t);
            mma8(Oacc[dn], aP[0][0], aP[0][1], aP[0][2], aP[0][3], U(v0.x), U(v0.y));
            mma8(Oacc[dn], aP[1][0], aP[1][1], aP[1][2], aP[1][3], U(v0.z), U(v0.w));
            mma8(Oacc[dn], aP[2][0], aP[2][1], aP[2][2], aP[2][3], U(v1.x), U(v1.y));
            mma8(Oacc[dn], aP[3][0], aP[3][1], aP[3][2], aP[3][3], U(v1.z), U(v1.w));
            mma8(Oacc[dn], aP[4][0], aP[4][1], aP[4][2], aP[4][3], U(v2.x), U(v2.y));
            mma8(Oacc[dn], aP[5][0], aP[5][1], aP[5][2], aP[5][3], U(v2.z), U(v2.w));
            mma8(Oacc[dn], aP[6][0], aP[6][1], aP[6][2], aP[6][3], U(v3.x), U(v3.y));
            mma8(Oacc[dn], aP[7][0], aP[7][1], aP[7][2], aP[7][3], U(v3.z), U(v3.w));
        }
    }

    float inv0 = 1.f / l0r, inv1 = 1.f / l1r;
    float* Og = g_O + (size_t)b * SEQ * DIM + (size_t)r0 * DIM + hcol;
#pragma unroll
    for (int dn = 0; dn < 8; dn++) {
        int d0 = dn * 8 + 2 * t;
        Og[(size_t)(rA)     * DIM + d0]     = Oacc[dn][0] * inv0;
        Og[(size_t)(rA)     * DIM + d0 + 1] = Oacc[dn][1] * inv0;
        Og[(size_t)(rA + 8) * DIM + d0]     = Oacc[dn][2] * inv1;
        Og[(size_t)(rA + 8) * DIM + d0 + 1] = Oacc[dn][3] * inv1;
    }
}

// ---------------- launch ----------------
extern "C" void kernel_launch(void* const* d_in, const int* in_sizes, int n_in,
                              void* d_out, int out_size)
{
    const float* x   = (const float*)d_in[0];
    const float* Wq  = (const float*)d_in[1];
    const float* Wk  = (const float*)d_in[2];
    const float* Wv  = (const float*)d_in[3];
    const float* Wp  = (const float*)d_in[4];
    const float* bp  = (const float*)d_in[5];
    const float* rel = (const float*)d_in[6];
    float* out = (float*)d_out;

    cudaFuncSetAttribute(attn_kernel,
                         cudaFuncAttributeMaxDynamicSharedMemorySize,
                         ATTN_SMEM_BYTES);

    float *d_xp, *d_Wqp, *d_Wkp, *d_Wvp, *d_Wpp;
    cudaGetSymbolAddress((void**)&d_xp,  g_xp);
    cudaGetSymbolAddress((void**)&d_Wqp, g_Wqp);
    cudaGetSymbolAddress((void**)&d_Wkp, g_Wkp);
    cudaGetSymbolAddress((void**)&d_Wvp, g_Wvp);
    cudaGetSymbolAddress((void**)&d_Wpp, g_Wpp);

    const int ngx = BN * DIM / 16;
    const int ngw = DIM * DIM / 16;
    permute_cvt<<<(ngx + 255) / 256, 256>>>(x,  d_xp,  ngx);
    permute_cvt<<<(ngw + 255) / 256, 256>>>(Wq, d_Wqp, ngw);
    permute_cvt<<<(ngw + 255) / 256, 256>>>(Wk, d_Wkp, ngw);
    permute_cvt<<<(ngw + 255) / 256, 256>>>(Wv, d_Wvp, ngw);
    permute_cvt<<<(ngw + 255) / 256, 256>>>(Wp, d_Wpp, ngw);
    const int nge = NHEAD * EROWS * 16;
    permute_E<<<(nge + 255) / 256, 256>>>(rel);

    gemm_tn<1><<<dim3(DIM / 128, BN / 128, 3), 256>>>(d_Wqp, d_Wkp, d_Wvp, nullptr, nullptr);
    attn_kernel<<<dim3(SEQ / 64, BATCH * NHEAD), 128, ATTN_SMEM_BYTES>>>();
    gemm_tn<0><<<dim3(DIM / 128, BN / 128), 256>>>(d_Wpp, nullptr, nullptr, bp, out);
}

// round 17
// speedup vs baseline: 2.1189x; 1.0261x over previous
#include <cuda_runtime.h>
#include <stdint.h>

#define BATCH   2
#define SEQ     2048
#define DIM     1024
#define NHEAD   16
#define HDIM    64
#define MAXLEN  2048
#define BN      (BATCH*SEQ)
#define EROWS   (SEQ + 128)

// ---------------- scratch (device globals; allocation is forbidden) ----------------
__device__ float g_Q  [(size_t)BATCH * NHEAD * SEQ * HDIM];  // linear [(bh)][n][hd]
__device__ float g_Kp [(size_t)BATCH * NHEAD * SEQ * HDIM];  // smem-image per (bh,tile)
__device__ float g_VTp[(size_t)BATCH * NHEAD * SEQ * HDIM];  // transposed smem-image, tf32
__device__ float g_O  [(size_t)BATCH * SEQ * DIM];           // raw fp32
__device__ float g_Ep [(size_t)NHEAD * EROWS * HDIM];        // per-head permuted E, zero-padded
// permuted + RNA-tf32 copies in the exact gemm smem image layout
__device__ float g_xp [(size_t)BN * DIM];
__device__ float g_Wqp[(size_t)DIM * DIM];
__device__ float g_Wkp[(size_t)DIM * DIM];
__device__ float g_Wvp[(size_t)DIM * DIM];
__device__ float g_Wpp[(size_t)DIM * DIM];

// ---------------- helpers ----------------
__device__ __forceinline__ uint32_t f2t(float f) {
    uint32_t u;
    asm("cvt.rna.tf32.f32 %0, %1;" : "=r"(u) : "f"(f));
    return u;
}
__device__ __forceinline__ float f2tf(float f) {
    return __uint_as_float(f2t(f));
}
__device__ __forceinline__ void mma8(float c[4],
                                     uint32_t a0, uint32_t a1, uint32_t a2, uint32_t a3,
                                     uint32_t b0, uint32_t b1) {
    asm volatile(
        "mma.sync.aligned.m16n8k8.row.col.f32.tf32.tf32.f32 "
        "{%0,%1,%2,%3},{%4,%5,%6,%7},{%8,%9},{%0,%1,%2,%3};"
        : "+f"(c[0]), "+f"(c[1]), "+f"(c[2]), "+f"(c[3])
        : "r"(a0), "r"(a1), "r"(a2), "r"(a3), "r"(b0), "r"(b1));
}
#define U(x) __float_as_uint(x)

__device__ __forceinline__ void cp16(uint32_t saddr, const float* gptr) {
    asm volatile("cp.async.cg.shared.global [%0], [%1], 16;" :: "r"(saddr), "l"(gptr));
}
#define CP_COMMIT() asm volatile("cp.async.commit_group;")
#define CP_WAIT0()  asm volatile("cp.async.wait_group 0;")
#define CP_WAIT1()  asm volatile("cp.async.wait_group 1;")
#define CP_WAIT2()  asm volatile("cp.async.wait_group 2;")

// chunk swizzle for 64-word permuted rows (uses row bits 0..2 only)
__device__ __forceinline__ int swz(int row) {
    return ((row & 1) << 2) | ((row >> 1) & 3);
}
// word index of element k within a permuted 64-word row
__device__ __forceinline__ int pword(int k, int row) {
    return 4 * ((4 * (k >> 4) + (k & 3)) ^ swz(row)) + ((k & 15) >> 2);
}
__device__ __forceinline__ void stash_perm(float* rowp, int c4, float4 v, int s) {
    int a4 = 4 * (c4 >> 4);
    int wd = (c4 & 15) >> 2;
    rowp[4 * ((a4 + 0) ^ s) + wd] = v.x;
    rowp[4 * ((a4 + 1) ^ s) + wd] = v.y;
    rowp[4 * ((a4 + 2) ^ s) + wd] = v.z;
    rowp[4 * ((a4 + 3) ^ s) + wd] = v.w;
}
__device__ __forceinline__ float4 frag4(const float* S, int stride, int row, int kb, int t) {
    return *(const float4*)&S[row * stride + 4 * ((4 * kb + t) ^ swz(row))];
}

// ---------------- prologue kernels ----------------
__global__ void permute_cvt(const float* __restrict__ src, float* __restrict__ dst,
                            int ngroups)
{
    int gi = blockIdx.x * 256 + threadIdx.x;
    if (gi >= ngroups) return;
    int row = gi >> 6;
    int sxb = (row >> 1) & 3;
    const float4* s = (const float4*)(src + (size_t)gi * 16);
    float4 v0 = s[0], v1 = s[1], v2 = s[2], v3 = s[3];
    float4* d = (float4*)(dst + (size_t)gi * 16);
    d[0 ^ sxb] = make_float4(f2tf(v0.x), f2tf(v1.x), f2tf(v2.x), f2tf(v3.x));
    d[1 ^ sxb] = make_float4(f2tf(v0.y), f2tf(v1.y), f2tf(v2.y), f2tf(v3.y));
    d[2 ^ sxb] = make_float4(f2tf(v0.z), f2tf(v1.z), f2tf(v2.z), f2tf(v3.z));
    d[3 ^ sxb] = make_float4(f2tf(v0.w), f2tf(v1.w), f2tf(v2.w), f2tf(v3.w));
}

__global__ void permute_E(const float* __restrict__ rel)
{
    int task = blockIdx.x * 256 + threadIdx.x;
    if (task >= NHEAD * EROWS * 16) return;
    int grp = task & 15;
    int L   = (task >> 4) % EROWS;
    int h   = task / (16 * EROWS);
    float4 v = make_float4(0.f, 0.f, 0.f, 0.f);
    if (L < SEQ)
        v = *(const float4*)(rel + (size_t)(L + (MAXLEN - SEQ)) * DIM + h * HDIM + grp * 4);
    stash_perm(g_Ep + ((size_t)h * EROWS + L) * 64, grp * 4, v, swz(L & 127));
}

// ---------------- QKV GEMM: 3-stage cp.async pipeline, dynamic smem ----------------
__global__ __launch_bounds__(256, 2)
void gemm_qkv3(const float* __restrict__ B0, const float* __restrict__ B1,
               const float* __restrict__ B2)
{
    extern __shared__ float gsm[];
    float* As = gsm;              // [3][2048]
    float* Bs = gsm + 3 * 2048;   // [3][2048]

    const int sel = blockIdx.z;
    const float* Bp = (sel == 0) ? B0 : ((sel == 1) ? B1 : B2);

    const int m0 = blockIdx.y * 128;
    const int n0 = blockIdx.x * 128;
    const int tid = threadIdx.x;
    const int w = tid >> 5, lane = tid & 31, g = lane >> 2, t = lane & 3;
    const int wy = w >> 2, wx = w & 3;

    const uint32_t sA = (uint32_t)__cvta_generic_to_shared(As);
    const uint32_t sB = (uint32_t)__cvta_generic_to_shared(Bs);

    auto issue = [&](int buf, int kb) {
#pragma unroll
        for (int r = 0; r < 2; r++) {
            int ch = tid + 256 * r;
            int row = ch >> 2, wg = ch & 3;
            cp16(sA + (uint32_t)(buf * 2048 + 4 * ch) * 4,
                 g_xp + (size_t)(m0 + row) * DIM + kb * 16 + wg * 4);
            cp16(sB + (uint32_t)(buf * 2048 + 4 * ch) * 4,
                 Bp + (size_t)(n0 + row) * DIM + kb * 16 + wg * 4);
        }
        CP_COMMIT();
    };

    float acc[4][4][4];
#pragma unroll
    for (int i = 0; i < 4; i++)
#pragma unroll
        for (int j = 0; j < 4; j++)
#pragma unroll
            for (int e = 0; e < 4; e++) acc[i][j][e] = 0.f;

    issue(0, 0);
    issue(1, 1);

    int cur = 0, nxt = 2;
    for (int kb = 0; kb < 64; kb++) {
        if (kb == 63) CP_WAIT0(); else CP_WAIT1();
        __syncthreads();
        if (kb + 2 < 64) issue(nxt, kb + 2);

        const float* A = As + cur * 2048;
        const float* B = Bs + cur * 2048;
        float4 fa[4][2], fb[4];
#pragma unroll
        for (int mt = 0; mt < 4; mt++) {
            int r = wy * 64 + mt * 16 + g;
            fa[mt][0] = *(const float4*)&A[r * 16 + 4 * (t ^ ((r >> 1) & 3))];
            int r2 = r + 8;
            fa[mt][1] = *(const float4*)&A[r2 * 16 + 4 * (t ^ ((r2 >> 1) & 3))];
        }
#pragma unroll
        for (int nt = 0; nt < 4; nt++) {
            int c = wx * 32 + nt * 8 + g;
            fb[nt] = *(const float4*)&B[c * 16 + 4 * (t ^ ((c >> 1) & 3))];
        }
#pragma unroll
        for (int mt = 0; mt < 4; mt++)
#pragma unroll
            for (int nt = 0; nt < 4; nt++) {
                mma8(acc[mt][nt], U(fa[mt][0].x), U(fa[mt][1].x),
                                  U(fa[mt][0].y), U(fa[mt][1].y),
                                  U(fb[nt].x),    U(fb[nt].y));
                mma8(acc[mt][nt], U(fa[mt][0].z), U(fa[mt][1].z),
                                  U(fa[mt][0].w), U(fa[mt][1].w),
                                  U(fb[nt].z),    U(fb[nt].w));
            }

        cur = (cur == 2) ? 0 : cur + 1;
        nxt = (nxt == 2) ? 0 : nxt + 1;
    }

#pragma unroll
    for (int mt = 0; mt < 4; mt++) {
        int rbase = wy * 64 + mt * 16 + g;
#pragma unroll
        for (int nt = 0; nt < 4; nt++) {
            int cbase = wx * 32 + nt * 8 + 2 * t;
#pragma unroll
            for (int e = 0; e < 4; e++) {
                int gm = m0 + rbase + ((e >= 2) ? 8 : 0);
                int gn = n0 + cbase + (e & 1);
                float v = acc[mt][nt][e];
                int bb = gm / SEQ, nrow = gm % SEQ;
                int hh = gn / HDIM, hd = gn % HDIM;
                int bh = bb * NHEAD + hh;
                int tile = nrow >> 6, tok = nrow & 63;
                if (sel == 0) {
                    g_Q[((size_t)bh * SEQ + nrow) * HDIM + hd] = v;
                } else if (sel == 1) {
                    g_Kp[(((size_t)bh * 32 + tile) * 64 + tok) * 64 + pword(hd, tok)] = v;
                } else {
                    g_VTp[(((size_t)bh * 32 + tile) * 64 + hd) * 64 + pword(tok, hd)] = f2tf(v);
                }
            }
        }
    }
}

// ---------------- output GEMM (2-stage; A = g_O raw via LDG+cvt+STS) ----------------
__global__ __launch_bounds__(256, 2)
void gemm_out(const float* __restrict__ Bp,
              const float* __restrict__ bias, float* __restrict__ Cext)
{
    __align__(16) __shared__ float As[2][128 * 16];
    __align__(16) __shared__ float Bs[2][128 * 16];

    const int m0 = blockIdx.y * 128;
    const int n0 = blockIdx.x * 128;
    const int tid = threadIdx.x;
    const int w = tid >> 5, lane = tid & 31, g = lane >> 2, t = lane & 3;
    const int wy = w >> 2, wx = w & 3;

    const uint32_t sB = (uint32_t)__cvta_generic_to_shared(&Bs[0][0]);

    const int srow = tid >> 2;
    const int sc   = tid & 3;
    const int sxb  = (srow >> 1) & 3;
    auto stageA = [&](float* S, int row, float4 v) {
        float* base = S + row * 16 + sc;
        base[4 * (0 ^ sxb)] = f2tf(v.x);
        base[4 * (1 ^ sxb)] = f2tf(v.y);
        base[4 * (2 ^ sxb)] = f2tf(v.z);
        base[4 * (3 ^ sxb)] = f2tf(v.w);
    };
    auto issueB = [&](int buf, int kb) {
#pragma unroll
        for (int r = 0; r < 2; r++) {
            int ch = tid + 256 * r;
            int row = ch >> 2, wg = ch & 3;
            cp16(sB + (uint32_t)(buf * 2048 + 4 * ch) * 4,
                 Bp + (size_t)(n0 + row) * DIM + kb * 16 + wg * 4);
        }
    };

    float acc[4][4][4];
#pragma unroll
    for (int i = 0; i < 4; i++)
#pragma unroll
        for (int j = 0; j < 4; j++)
#pragma unroll
            for (int e = 0; e < 4; e++) acc[i][j][e] = 0.f;

    float4 ra0, ra1;
    issueB(0, 0);
    CP_COMMIT();
    ra0 = *(const float4*)(g_O + (size_t)(m0 + srow)      * DIM + 4 * sc);
    ra1 = *(const float4*)(g_O + (size_t)(m0 + srow + 64) * DIM + 4 * sc);
    stageA(&As[0][0], srow,      ra0);
    stageA(&As[0][0], srow + 64, ra1);
    CP_WAIT0();
    __syncthreads();

    for (int kb = 0; kb < 64; kb++) {
        const int cur = kb & 1;
        const bool more = (kb + 1 < 64);
        if (more) {
            issueB(cur ^ 1, kb + 1);
            CP_COMMIT();
            ra0 = *(const float4*)(g_O + (size_t)(m0 + srow)      * DIM + (kb + 1) * 16 + 4 * sc);
            ra1 = *(const float4*)(g_O + (size_t)(m0 + srow + 64) * DIM + (kb + 1) * 16 + 4 * sc);
        }

        float4 fa[4][2], fb[4];
#pragma unroll
        for (int mt = 0; mt < 4; mt++) {
            int r = wy * 64 + mt * 16 + g;
            fa[mt][0] = *(float4*)&As[cur][r * 16 + 4 * (t ^ ((r >> 1) & 3))];
            int r2 = r + 8;
            fa[mt][1] = *(float4*)&As[cur][r2 * 16 + 4 * (t ^ ((r2 >> 1) & 3))];
        }
#pragma unroll
        for (int nt = 0; nt < 4; nt++) {
            int c = wx * 32 + nt * 8 + g;
            fb[nt] = *(float4*)&Bs[cur][c * 16 + 4 * (t ^ ((c >> 1) & 3))];
        }
#pragma unroll
        for (int mt = 0; mt < 4; mt++)
#pragma unroll
            for (int nt = 0; nt < 4; nt++) {
                mma8(acc[mt][nt], U(fa[mt][0].x), U(fa[mt][1].x),
                                  U(fa[mt][0].y), U(fa[mt][1].y),
                                  U(fb[nt].x),    U(fb[nt].y));
                mma8(acc[mt][nt], U(fa[mt][0].z), U(fa[mt][1].z),
                                  U(fa[mt][0].w), U(fa[mt][1].w),
                                  U(fb[nt].z),    U(fb[nt].w));
            }

        if (more) {
            stageA(&As[cur ^ 1][0], srow,      ra0);
            stageA(&As[cur ^ 1][0], srow + 64, ra1);
            CP_WAIT0();
        }
        __syncthreads();
    }

#pragma unroll
    for (int mt = 0; mt < 4; mt++) {
        int rbase = wy * 64 + mt * 16 + g;
#pragma unroll
        for (int nt = 0; nt < 4; nt++) {
            int cbase = wx * 32 + nt * 8 + 2 * t;
#pragma unroll
            for (int e = 0; e < 4; e++) {
                int gm = m0 + rbase + ((e >= 2) ? 8 : 0);
                int gn = n0 + cbase + (e & 1);
                Cext[(size_t)gm * DIM + gn] = acc[mt][nt][e] + bias[gn];
            }
        }
    }
}

// ---------------- fused causal attention with skewed relative positions ----------------
// Staged waits: group E -> G band; group K -> S/softmax; group VT -> PV.
#define GBW 65
#define ATTN_SMEM_FLOATS (65*64 + 64*64 + 64*64 + 128*64 + 64*GBW)
#define ATTN_SMEM_BYTES  (ATTN_SMEM_FLOATS * 4)
#define SCL (0.125f * 1.44269504088896f)   // 1/sqrt(64) * log2(e); softmax via exp2

__global__ __launch_bounds__(128, 2)
void attn_kernel()
{
    extern __shared__ float sm[];
    float* sQ  = sm;                    // [65][64] perm tf32; reused as P
    float* sK  = sQ + 65 * 64;          // [64][64]
    float* sVT = sK + 64 * 64;          // [64][64] V^T, tf32
    float* sE  = sVT + 64 * 64;         // [128][64] ring, slot = L&127
    float* sGb = sE + 128 * 64;         // [64][GBW] G band
    float* sP  = sQ;

    const uint32_t aK  = (uint32_t)__cvta_generic_to_shared(sK);
    const uint32_t aVT = (uint32_t)__cvta_generic_to_shared(sVT);
    const uint32_t aE  = (uint32_t)__cvta_generic_to_shared(sE);

    const int qt = (gridDim.x - 1) - blockIdx.x;   // 31..0 (long CTAs first)
    const int bh = blockIdx.y;
    const int r0 = qt * 64;
    const int b  = bh / NHEAD;
    const int h  = bh % NHEAD;
    const int hcol = h * HDIM;

    const float* Qg  = g_Q   + (size_t)bh * SEQ * HDIM;
    const float* Kpg = g_Kp  + (size_t)bh * 32 * 4096;
    const float* VTg = g_VTp + (size_t)bh * 32 * 4096;
    const float* Epg = g_Ep  + (size_t)h * EROWS * 64;

    const int tid = threadIdx.x;
    const int w = tid >> 5, lane = tid & 31, g = lane >> 2, t = lane & 3;
    const int rA = w * 16 + g;

    for (int idx = tid; idx < 65 * 16; idx += 128) {
        int row = idx >> 4, c4 = (idx & 15) << 2;
        int gr = r0 - 1 + row; if (gr < 0) gr = 0;
        float4 v = *(const float4*)(Qg + (size_t)gr * HDIM + c4);
        stash_perm(sQ + row * 64, c4,
                   make_float4(f2tf(v.x), f2tf(v.y), f2tf(v.z), f2tf(v.w)),
                   swz(row));
    }
    __syncthreads();

    uint32_t aQ[8][4], aQp[8][4];
#pragma unroll
    for (int kb = 0; kb < 4; kb++) {
        float4 f;
        f = frag4(sQ, 64, 1 + rA, kb, t);
        aQ[2*kb][0] = U(f.x); aQ[2*kb][2] = U(f.y);
        aQ[2*kb+1][0] = U(f.z); aQ[2*kb+1][2] = U(f.w);
        f = frag4(sQ, 64, 9 + rA, kb, t);
        aQ[2*kb][1] = U(f.x); aQ[2*kb][3] = U(f.y);
        aQ[2*kb+1][1] = U(f.z); aQ[2*kb+1][3] = U(f.w);
        f = frag4(sQ, 64, rA, kb, t);
        aQp[2*kb][0] = U(f.x); aQp[2*kb][2] = U(f.y);
        aQp[2*kb+1][0] = U(f.z); aQp[2*kb+1][2] = U(f.w);
        f = frag4(sQ, 64, 8 + rA, kb, t);
        aQp[2*kb][1] = U(f.x); aQp[2*kb][3] = U(f.y);
        aQp[2*kb+1][1] = U(f.z); aQp[2*kb+1][3] = U(f.w);
    }

    float Oacc[8][4];
#pragma unroll
    for (int i = 0; i < 8; i++)
#pragma unroll
        for (int e = 0; e < 4; e++) Oacc[i][e] = 0.f;
    float m0r = -1e30f, m1r = -1e30f;
    float l0r = 0.f,    l1r = 0.f;

    for (int j = 0; j <= qt; j++) {
        const int c0 = j * 64;
        const int elog0 = SEQ - r0 + c0 - 63;   // >= 1 always
        __syncthreads();   // previous iteration's smem readers done

        // ---- group 1: E ring ----
        if (j == 0) {
#pragma unroll
            for (int r = 0; r < 16; r++) {
                int ch = tid + 128 * r;
                int er = ch >> 4, cw = ch & 15;
                int L = elog0 + er;
                cp16(aE + (uint32_t)(((L & 127) * 64 + cw * 4)) * 4,
                     Epg + (size_t)L * 64 + cw * 4);
            }
        } else {
#pragma unroll
            for (int r = 0; r < 8; r++) {
                int ch = tid + 128 * r;
                int er = 64 + (ch >> 4), cw = ch & 15;
                int L = elog0 + er;
                cp16(aE + (uint32_t)(((L & 127) * 64 + cw * 4)) * 4,
                     Epg + (size_t)L * 64 + cw * 4);
            }
        }
        CP_COMMIT();
        // ---- group 2: K ----
#pragma unroll
        for (int r = 0; r < 8; r++) {
            int ch = tid + 128 * r;
            cp16(aK + (uint32_t)ch * 16, Kpg + (size_t)j * 4096 + ch * 4);
        }
        CP_COMMIT();
        // ---- group 3: V^T ----
#pragma unroll
        for (int r = 0; r < 8; r++) {
            int ch = tid + 128 * r;
            cp16(aVT + (uint32_t)ch * 16, VTg + (size_t)j * 4096 + ch * 4);
        }
        CP_COMMIT();

        CP_WAIT2();          // E complete; K/VT still in flight
        __syncthreads();

        // ---- G band = Qprev @ Ewin^T (warp-trimmed n-tiles) ----
        const int nt0 = 6 - 2 * w;
#pragma unroll
        for (int ntl = 0; ntl < 10; ntl++) {
            const int nt = nt0 + ntl;
            float ga[4] = {0.f, 0.f, 0.f, 0.f};
            const int slot = (elog0 + nt * 8 + g) & 127;
            float4 f0 = frag4(sE, 64, slot, 0, t);
            float4 f1 = frag4(sE, 64, slot, 1, t);
            float4 f2 = frag4(sE, 64, slot, 2, t);
            float4 f3 = frag4(sE, 64, slot, 3, t);
            mma8(ga, aQp[0][0], aQp[0][1], aQp[0][2], aQp[0][3], U(f0.x), U(f0.y));
            mma8(ga, aQp[1][0], aQp[1][1], aQp[1][2], aQp[1][3], U(f0.z), U(f0.w));
            mma8(ga, aQp[2][0], aQp[2][1], aQp[2][2], aQp[2][3], U(f1.x), U(f1.y));
            mma8(ga, aQp[3][0], aQp[3][1], aQp[3][2], aQp[3][3], U(f1.z), U(f1.w));
            mma8(ga, aQp[4][0], aQp[4][1], aQp[4][2], aQp[4][3], U(f2.x), U(f2.y));
            mma8(ga, aQp[5][0], aQp[5][1], aQp[5][2], aQp[5][3], U(f2.z), U(f2.w));
            mma8(ga, aQp[6][0], aQp[6][1], aQp[6][2], aQp[6][3], U(f3.x), U(f3.y));
            mma8(ga, aQp[7][0], aQp[7][1], aQp[7][2], aQp[7][3], U(f3.z), U(f3.w));
            const int cc = nt * 8 + 2 * t;
            const int i0 = cc + rA - 63;
            const int i2 = i0 + 8;
            if (i0 >= 0     && i0 < 64)     sGb[(rA)     * GBW + i0]     = ga[0];
            if (i0 + 1 >= 0 && i0 + 1 < 64) sGb[(rA)     * GBW + i0 + 1] = ga[1];
            if (i2 >= 0     && i2 < 64)     sGb[(rA + 8) * GBW + i2]     = ga[2];
            if (i2 + 1 >= 0 && i2 + 1 < 64) sGb[(rA + 8) * GBW + i2 + 1] = ga[3];
        }
        __syncwarp();

        CP_WAIT1();          // K complete; VT still in flight
        __syncthreads();

        // ---- S = Q @ K^T + srel (band gather), mask, scale ----
        float Sreg[8][4];
        float tmax0 = -1e30f, tmax1 = -1e30f;
#pragma unroll
        for (int nt = 0; nt < 8; nt++) {
            float* s = Sreg[nt];
            s[0] = s[1] = s[2] = s[3] = 0.f;
            const int kr = nt * 8 + g;
            float4 f0 = frag4(sK, 64, kr, 0, t);
            float4 f1 = frag4(sK, 64, kr, 1, t);
            float4 f2 = frag4(sK, 64, kr, 2, t);
            float4 f3 = frag4(sK, 64, kr, 3, t);
            mma8(s, aQ[0][0], aQ[0][1], aQ[0][2], aQ[0][3], U(f0.x), U(f0.y));
            mma8(s, aQ[1][0], aQ[1][1], aQ[1][2], aQ[1][3], U(f0.z), U(f0.w));
            mma8(s, aQ[2][0], aQ[2][1], aQ[2][2], aQ[2][3], U(f1.x), U(f1.y));
            mma8(s, aQ[3][0], aQ[3][1], aQ[3][2], aQ[3][3], U(f1.z), U(f1.w));
            mma8(s, aQ[4][0], aQ[4][1], aQ[4][2], aQ[4][3], U(f2.x), U(f2.y));
            mma8(s, aQ[5][0], aQ[5][1], aQ[5][2], aQ[5][3], U(f2.z), U(f2.w));
            mma8(s, aQ[6][0], aQ[6][1], aQ[6][2], aQ[6][3], U(f3.x), U(f3.y));
            mma8(s, aQ[7][0], aQ[7][1], aQ[7][2], aQ[7][3], U(f3.z), U(f3.w));

            const int cc0 = nt * 8 + 2 * t;
            float v;
            v = (s[0] + sGb[rA * GBW + cc0]) * SCL;
            if (c0 + cc0 > r0 + rA) v = -1e30f;
            s[0] = v; tmax0 = fmaxf(tmax0, v);

            v = (s[1] + sGb[rA * GBW + cc0 + 1]) * SCL;
            if (c0 + cc0 + 1 > r0 + rA) v = -1e30f;
            s[1] = v; tmax0 = fmaxf(tmax0, v);

            v = (s[2] + sGb[(rA + 8) * GBW + cc0]) * SCL;
            if (c0 + cc0 > r0 + rA + 8) v = -1e30f;
            s[2] = v; tmax1 = fmaxf(tmax1, v);

            v = (s[3] + sGb[(rA + 8) * GBW + cc0 + 1]) * SCL;
            if (c0 + cc0 + 1 > r0 + rA + 8) v = -1e30f;
            s[3] = v; tmax1 = fmaxf(tmax1, v);
        }

        tmax0 = fmaxf(tmax0, __shfl_xor_sync(0xffffffffu, tmax0, 1));
        tmax0 = fmaxf(tmax0, __shfl_xor_sync(0xffffffffu, tmax0, 2));
        tmax1 = fmaxf(tmax1, __shfl_xor_sync(0xffffffffu, tmax1, 1));
        tmax1 = fmaxf(tmax1, __shfl_xor_sync(0xffffffffu, tmax1, 2));

        float mn0 = fmaxf(m0r, tmax0), mn1 = fmaxf(m1r, tmax1);
        float f0s = exp2f(m0r - mn0), f1s = exp2f(m1r - mn1);
        float rs0 = 0.f, rs1 = 0.f;
#pragma unroll
        for (int nt = 0; nt < 8; nt++) {
            float* s = Sreg[nt];
            s[0] = exp2f(s[0] - mn0); s[1] = exp2f(s[1] - mn0);
            s[2] = exp2f(s[2] - mn1); s[3] = exp2f(s[3] - mn1);
            rs0 += s[0] + s[1];
            rs1 += s[2] + s[3];
        }
        rs0 += __shfl_xor_sync(0xffffffffu, rs0, 1);
        rs0 += __shfl_xor_sync(0xffffffffu, rs0, 2);
        rs1 += __shfl_xor_sync(0xffffffffu, rs1, 1);
        rs1 += __shfl_xor_sync(0xffffffffu, rs1, 2);

        m0r = mn0; m1r = mn1;
        l0r = l0r * f0s + rs0;
        l1r = l1r * f1s + rs1;
#pragma unroll
        for (int dn = 0; dn < 8; dn++) {
            Oacc[dn][0] *= f0s; Oacc[dn][1] *= f0s;
            Oacc[dn][2] *= f1s; Oacc[dn][3] *= f1s;
        }

        __syncwarp();
#pragma unroll
        for (int nt = 0; nt < 8; nt++) {
            int c = nt * 8 + 2 * t;
            int ch = 4 * (c >> 4) + (c & 3);
            int wd = (c & 15) >> 2;
            int s0 = swz(rA), s1 = swz(rA + 8);
            sP[(rA)     * 64 + 4 * ((ch)     ^ s0) + wd] = f2tf(Sreg[nt][0]);
            sP[(rA)     * 64 + 4 * ((ch + 1) ^ s0) + wd] = f2tf(Sreg[nt][1]);
            sP[(rA + 8) * 64 + 4 * ((ch)     ^ s1) + wd] = f2tf(Sreg[nt][2]);
            sP[(rA + 8) * 64 + 4 * ((ch + 1) ^ s1) + wd] = f2tf(Sreg[nt][3]);
        }
        __syncwarp();

        uint32_t aP[8][4];
#pragma unroll
        for (int kb = 0; kb < 4; kb++) {
            float4 f;
            f = frag4(sP, 64, rA, kb, t);
            aP[2*kb][0] = U(f.x); aP[2*kb][2] = U(f.y);
            aP[2*kb+1][0] = U(f.z); aP[2*kb+1][2] = U(f.w);
            f = frag4(sP, 64, rA + 8, kb, t);
            aP[2*kb][1] = U(f.x); aP[2*kb][3] = U(f.y);
            aP[2*kb+1][1] = U(f.z); aP[2*kb+1][3] = U(f.w);
        }

        CP_WAIT0();          // V^T complete
        __syncthreads();

        // ---- O += P @ V ----
#pragma unroll
        for (int dn = 0; dn < 8; dn++) {
            const int nb = dn * 8 + g;
            float4 v0 = frag4(sVT, 64, nb, 0, t);
            float4 v1 = frag4(sVT, 64, nb, 1, t);
            float4 v2 = frag4(sVT, 64, nb, 2, t);
            float4 v3 = frag4(sVT, 64, nb, 3, t);
            mma8(Oacc[dn], aP[0][0], aP[0][1], aP[0][2], aP[0][3], U(v0.x), U(v0.y));
            mma8(Oacc[dn], aP[1][0], aP[1][1], aP[1][2], aP[1][3], U(v0.z), U(v0.w));
            mma8(Oacc[dn], aP[2][0], aP[2][1], aP[2][2], aP[2][3], U(v1.x), U(v1.y));
            mma8(Oacc[dn], aP[3][0], aP[3][1], aP[3][2], aP[3][3], U(v1.z), U(v1.w));
            mma8(Oacc[dn], aP[4][0], aP[4][1], aP[4][2], aP[4][3], U(v2.x), U(v2.y));
            mma8(Oacc[dn], aP[5][0], aP[5][1], aP[5][2], aP[5][3], U(v2.z), U(v2.w));
            mma8(Oacc[dn], aP[6][0], aP[6][1], aP[6][2], aP[6][3], U(v3.x), U(v3.y));
            mma8(Oacc[dn], aP[7][0], aP[7][1], aP[7][2], aP[7][3], U(v3.z), U(v3.w));
        }
    }

    float inv0 = 1.f / l0r, inv1 = 1.f / l1r;
    float* Og = g_O + (size_t)b * SEQ * DIM + (size_t)r0 * DIM + hcol;
#pragma unroll
    for (int dn = 0; dn < 8; dn++) {
        int d0 = dn * 8 + 2 * t;
        Og[(size_t)(rA)     * DIM + d0]     = Oacc[dn][0] * inv0;
        Og[(size_t)(rA)     * DIM + d0 + 1] = Oacc[dn][1] * inv0;
        Og[(size_t)(rA + 8) * DIM + d0]     = Oacc[dn][2] * inv1;
        Og[(size_t)(rA + 8) * DIM + d0 + 1] = Oacc[dn][3] * inv1;
    }
}

// ---------------- launch ----------------
#define QKV3_SMEM_BYTES (6 * 2048 * 4)

extern "C" void kernel_launch(void* const* d_in, const int* in_sizes, int n_in,
                              void* d_out, int out_size)
{
    const float* x   = (const float*)d_in[0];
    const float* Wq  = (const float*)d_in[1];
    const float* Wk  = (const float*)d_in[2];
    const float* Wv  = (const float*)d_in[3];
    const float* Wp  = (const float*)d_in[4];
    const float* bp  = (const float*)d_in[5];
    const float* rel = (const float*)d_in[6];
    float* out = (float*)d_out;

    cudaFuncSetAttribute(attn_kernel,
                         cudaFuncAttributeMaxDynamicSharedMemorySize, ATTN_SMEM_BYTES);
    cudaFuncSetAttribute(gemm_qkv3,
                         cudaFuncAttributeMaxDynamicSharedMemorySize, QKV3_SMEM_BYTES);

    float *d_xp, *d_Wqp, *d_Wkp, *d_Wvp, *d_Wpp;
    cudaGetSymbolAddress((void**)&d_xp,  g_xp);
    cudaGetSymbolAddress((void**)&d_Wqp, g_Wqp);
    cudaGetSymbolAddress((void**)&d_Wkp, g_Wkp);
    cudaGetSymbolAddress((void**)&d_Wvp, g_Wvp);
    cudaGetSymbolAddress((void**)&d_Wpp, g_Wpp);

    const int ngx = BN * DIM / 16;
    const int ngw = DIM * DIM / 16;
    permute_cvt<<<(ngx + 255) / 256, 256>>>(x,  d_xp,  ngx);
    permute_cvt<<<(ngw + 255) / 256, 256>>>(Wq, d_Wqp, ngw);
    permute_cvt<<<(ngw + 255) / 256, 256>>>(Wk, d_Wkp, ngw);
    permute_cvt<<<(ngw + 255) / 256, 256>>>(Wv, d_Wvp, ngw);
    permute_cvt<<<(ngw + 255) / 256, 256>>>(Wp, d_Wpp, ngw);
    const int nge = NHEAD * EROWS * 16;
    permute_E<<<(nge + 255) / 256, 256>>>(rel);

    gemm_qkv3<<<dim3(DIM / 128, BN / 128, 3), 256, QKV3_SMEM_BYTES>>>(d_Wqp, d_Wkp, d_Wvp);
    attn_kernel<<<dim3(SEQ / 64, BATCH * NHEAD), 128, ATTN_SMEM_BYTES>>>();
    gemm_out<<<dim3(DIM / 128, BN / 128), 256>>>(d_Wpp, bp, out);
}